// round 12
// baseline (speedup 1.0000x reference)
#include <cuda_runtime.h>
#include <cuda_fp16.h>
#include <math.h>
#include <stdint.h>

// ---------------- problem constants ----------------
#define SEQ   2048
#define HDIM  2048
#define NHEAD 16
#define DQK   192
#define DV    128
#define NOPE  128
#define ROPED 64
#define QRNK  768
#define KVRNK 512
#define NEXP  16
#define TOPK  4
#define MINT  1024
#define NSLOT (SEQ*TOPK)

// GEMM tiling (fp16, m16n8k16), 3-stage pipeline
#define BM 128
#define BN 128
#define BK 64
#define SKS 72
#define NSTG 3
#define GSMEM (NSTG*(BM+BN)*SKS*2)

// attention tiling (double-buffered K/V)
#define AQ 128
#define AK 64
#define QST 200
#define KST 200
#define VST 136
#define PST 72
#define ATTN_SMEM ((AQ*QST + 2*AK*KST + 2*AK*VST + AQ*PST)*2)

// ---------------- fp32 scratch ----------------
__device__ float g_qa[SEQ*QRNK];
__device__ float g_kva[SEQ*KVRNK];
__device__ float g_xmid[SEQ*HDIM];
__device__ float g_h2f[SEQ*HDIM];
__device__ float g_shr[SEQ*HDIM];
__device__ float g_logits[SEQ*NEXP];
__device__ float g_wtop[SEQ*TOPK];
__device__ int   g_topi[SEQ*TOPK];
__device__ int   g_slot[SEQ*TOPK];
__device__ int   g_cnt[NEXP];
__device__ int   g_off[NEXP+1];
__device__ int   g_fill[NEXP];
__device__ int   g_tok[NSLOT];

// ---------------- fp16 weights ----------------
__device__ __half w_qa[QRNK*HDIM];
__device__ __half w_kva[KVRNK*HDIM];
__device__ __half w_qb[NHEAD*DQK*QRNK];
__device__ __half w_kvb[NHEAD*(DQK+DV)*KVRNK];
__device__ __half w_o[HDIM*NHEAD*DV];
__device__ __half w_gate[(size_t)NEXP*MINT*HDIM];
__device__ __half w_up[(size_t)NEXP*MINT*HDIM];
__device__ __half w_down[(size_t)NEXP*HDIM*MINT];
__device__ __half w_sg[MINT*HDIM];
__device__ __half w_su[MINT*HDIM];
__device__ __half w_sd[HDIM*MINT];

// ---------------- fp16 activations ----------------
__device__ __half a_h1[SEQ*HDIM];
__device__ __half a_qa[SEQ*QRNK];
__device__ __half a_kva[SEQ*KVRNK];
__device__ __half a_q[SEQ*NHEAD*DQK];
__device__ __half a_kv[SEQ*NHEAD*(DQK+DV)];
__device__ __half a_ctx[SEQ*NHEAD*DV];
__device__ __half a_h2[SEQ*HDIM];
__device__ __half a_gate[(size_t)NSLOT*MINT];
__device__ __half a_up[(size_t)NSLOT*MINT];
__device__ __half a_down[(size_t)NSLOT*HDIM];
__device__ __half a_sg[SEQ*MINT];
__device__ __half a_su[SEQ*MINT];

// ---------------- helpers ----------------
__device__ __forceinline__ void cp16(uint32_t dst, const void* src, int szbytes) {
    asm volatile("cp.async.cg.shared.global [%0], [%1], 16, %2;\n"
                 :: "r"(dst), "l"(src), "r"(szbytes));
}
__device__ __forceinline__ void cp_commit() { asm volatile("cp.async.commit_group;\n"); }
__device__ __forceinline__ void cp_wait0()  { asm volatile("cp.async.wait_group 0;\n"); }
__device__ __forceinline__ void cp_wait1()  { asm volatile("cp.async.wait_group 1;\n"); }

__device__ __forceinline__ void mma_h(float* c, const uint32_t* a, const uint32_t* b) {
    asm volatile(
        "mma.sync.aligned.m16n8k16.row.col.f32.f16.f16.f32 "
        "{%0,%1,%2,%3}, {%4,%5,%6,%7}, {%8,%9}, {%0,%1,%2,%3};\n"
        : "+f"(c[0]), "+f"(c[1]), "+f"(c[2]), "+f"(c[3])
        : "r"(a[0]), "r"(a[1]), "r"(a[2]), "r"(a[3]), "r"(b[0]), "r"(b[1]));
}
__device__ __forceinline__ void ldm_x4(uint32_t* r, uint32_t addr) {
    asm volatile("ldmatrix.sync.aligned.m8n8.x4.shared.b16 {%0,%1,%2,%3}, [%4];"
                 : "=r"(r[0]), "=r"(r[1]), "=r"(r[2]), "=r"(r[3]) : "r"(addr));
}
__device__ __forceinline__ void ldm_x4_t(uint32_t* r, uint32_t addr) {
    asm volatile("ldmatrix.sync.aligned.m8n8.x4.trans.shared.b16 {%0,%1,%2,%3}, [%4];"
                 : "=r"(r[0]), "=r"(r[1]), "=r"(r[2]), "=r"(r[3]) : "r"(addr));
}

// ---------------- batched fp32 -> fp16 convert ----------------
#define NSEG 6
struct ConvBatch {
    const float4* in[NSEG];
    __half* out[NSEG];
    int start[NSEG + 1];
};
__global__ void conv_batch_kernel(ConvBatch cb) {
    int i = blockIdx.x * blockDim.x + threadIdx.x;
    if (i >= cb.start[NSEG]) return;
    int seg = 0;
#pragma unroll
    for (int s = 1; s < NSEG; s++) seg += (i >= cb.start[s]);
    int local = i - cb.start[seg];
    float4 v = __ldcs(cb.in[seg] + local);
    __half2 p[2];
    p[0] = __floats2half2_rn(v.x, v.y);
    p[1] = __floats2half2_rn(v.z, v.w);
    __stcs((float2*)(cb.out[seg] + (size_t)local * 4), *(float2*)p);
}

// ---------------- fp16 tensor-core GEMM (dual segment, 3-stage) ----------------
__global__ __launch_bounds__(256, 2) void gemm_h(
    const __half* __restrict__ A1,
    const __half* __restrict__ B1, float* C1, __half* C1h, const float* add1, int N1, int K1,
    const __half* __restrict__ A2,
    const __half* __restrict__ B2, float* C2, __half* C2h, int N2, int K2,
    int M)
{
    extern __shared__ __half smh[];

    int n0 = blockIdx.x * BN;
    const __half *A, *B; float* C; __half* Ch; const float* addsrc; int N, K;
    if (n0 < N1) { A = A1; B = B1; C = C1; Ch = C1h; addsrc = add1; N = N1; K = K1; }
    else { n0 -= N1; A = A2; B = B2; C = C2; Ch = C2h; addsrc = nullptr; N = N2; K = K2; }

    const int tid = threadIdx.x;
    const int warp = tid >> 5, lane = tid & 31;
    const int g = lane >> 2, tig = lane & 3;
    const int warp_m = (warp & 1) * 64, warp_n = (warp >> 1) * 32;
    const int m0 = blockIdx.y * BM;

    float acc[4][4][4];
#pragma unroll
    for (int a = 0; a < 4; a++)
#pragma unroll
        for (int b = 0; b < 4; b++)
#pragma unroll
            for (int c = 0; c < 4; c++) acc[a][b][c] = 0.f;

    const int nk = K / BK;
    uint32_t smA[NSTG], smB[NSTG];
#pragma unroll
    for (int s = 0; s < NSTG; s++) {
        smA[s] = (uint32_t)__cvta_generic_to_shared(smh + s * BM * SKS);
        smB[s] = (uint32_t)__cvta_generic_to_shared(smh + NSTG * BM * SKS + s * BN * SKS);
    }

    const int ldrow = tid >> 3, ldc8 = (tid & 7) << 3;
    const uint32_t aoff = ((warp_m + (lane & 15)) * SKS + ((lane >> 4) << 3)) * 2;
    const uint32_t boff = ((warp_n + ((lane >> 4) & 1) * 8 + (lane & 7)) * SKS
                           + (((lane >> 3) & 1) << 3)) * 2;

#pragma unroll
    for (int s = 0; s < 2; s++) {
        int k0 = s * BK;
#pragma unroll
        for (int i = 0; i < 4; i++) {
            int row = ldrow + i * 32;
            cp16(smA[s] + (row * SKS + ldc8) * 2, A + (size_t)(m0 + row) * K + k0 + ldc8, 16);
        }
#pragma unroll
        for (int i = 0; i < 4; i++) {
            int row = ldrow + i * 32;
            cp16(smB[s] + (row * SKS + ldc8) * 2, B + (size_t)(n0 + row) * K + k0 + ldc8, 16);
        }
        cp_commit();
    }

    int cur = 0, pf = 2;
    for (int kt = 0; kt < nk; kt++) {
        cp_wait1();
        __syncthreads();
        if (kt + 2 < nk) {
            int k0 = (kt + 2) * BK;
#pragma unroll
            for (int i = 0; i < 4; i++) {
                int row = ldrow + i * 32;
                cp16(smA[pf] + (row * SKS + ldc8) * 2, A + (size_t)(m0 + row) * K + k0 + ldc8, 16);
            }
#pragma unroll
            for (int i = 0; i < 4; i++) {
                int row = ldrow + i * 32;
                cp16(smB[pf] + (row * SKS + ldc8) * 2, B + (size_t)(n0 + row) * K + k0 + ldc8, 16);
            }
        }
        cp_commit();

        const uint32_t sA = smA[cur], sB = smB[cur];
#pragma unroll
        for (int ks = 0; ks < 4; ks++) {
            const uint32_t kk2 = ks * 32;
            uint32_t af[4][4], bf[4][2];
#pragma unroll
            for (int mt = 0; mt < 4; mt++)
                ldm_x4(af[mt], sA + aoff + mt * 16 * SKS * 2 + kk2);
#pragma unroll
            for (int ntp = 0; ntp < 2; ntp++) {
                uint32_t tmp[4];
                ldm_x4(tmp, sB + boff + ntp * 16 * SKS * 2 + kk2);
                bf[2 * ntp][0] = tmp[0]; bf[2 * ntp][1] = tmp[1];
                bf[2 * ntp + 1][0] = tmp[2]; bf[2 * ntp + 1][1] = tmp[3];
            }
#pragma unroll
            for (int mt = 0; mt < 4; mt++)
#pragma unroll
                for (int nt = 0; nt < 4; nt++)
                    mma_h(acc[mt][nt], af[mt], bf[nt]);
        }
        cur = (cur + 1 == NSTG) ? 0 : cur + 1;
        pf = (pf + 1 == NSTG) ? 0 : pf + 1;
    }

#pragma unroll
    for (int mt = 0; mt < 4; mt++) {
        int r0 = m0 + warp_m + mt * 16 + g;
#pragma unroll
        for (int nt = 0; nt < 4; nt++) {
            int gc = n0 + warp_n + nt * 8 + tig * 2;
            float v0 = acc[mt][nt][0], v1 = acc[mt][nt][1];
            float v2 = acc[mt][nt][2], v3 = acc[mt][nt][3];
            if (addsrc) {
                v0 += addsrc[(size_t)r0 * N + gc];
                v1 += addsrc[(size_t)r0 * N + gc + 1];
                v2 += addsrc[(size_t)(r0 + 8) * N + gc];
                v3 += addsrc[(size_t)(r0 + 8) * N + gc + 1];
            }
            if (C) {
                *(float2*)(C + (size_t)r0 * N + gc) = make_float2(v0, v1);
                *(float2*)(C + (size_t)(r0 + 8) * N + gc) = make_float2(v2, v3);
            }
            if (Ch) {
                *(__half2*)(Ch + (size_t)r0 * N + gc) = __floats2half2_rn(v0, v1);
                *(__half2*)(Ch + (size_t)(r0 + 8) * N + gc) = __floats2half2_rn(v2, v3);
            }
        }
    }
}

// ---------------- fp16 grouped MoE GEMM (dual-B, gathered A, 3-stage) ----------------
__global__ __launch_bounds__(256, 2) void gemm_h_moe(
    const __half* __restrict__ A, const int* __restrict__ gather,
    const __half* __restrict__ B1b, __half* C1h, int N1,
    const __half* __restrict__ B2b, __half* C2h, int N2,
    size_t strideB, int K, const int* __restrict__ off)
{
    const int e = blockIdx.z;
    const int start = off[e];
    const int cnt = off[e + 1] - start;
    const int m0 = blockIdx.y * BM;
    if (m0 >= cnt) return;

    int n0 = blockIdx.x * BN;
    const __half* B; __half* Ch; int N;
    if (n0 < N1) { B = B1b + (size_t)e * strideB; Ch = C1h; N = N1; }
    else { n0 -= N1; B = B2b + (size_t)e * strideB; Ch = C2h; N = N2; }

    extern __shared__ __half smh[];
    __shared__ int rowmap[BM];

    const int tid = threadIdx.x;
    if (tid < BM) {
        int r = m0 + tid;
        int gr = -1;
        if (r < cnt) gr = gather ? gather[start + r] : (start + r);
        rowmap[tid] = gr;
    }
    __syncthreads();

    const int warp = tid >> 5, lane = tid & 31;
    const int g = lane >> 2, tig = lane & 3;
    const int warp_m = (warp & 1) * 64, warp_n = (warp >> 1) * 32;

    float acc[4][4][4];
#pragma unroll
    for (int a = 0; a < 4; a++)
#pragma unroll
        for (int b = 0; b < 4; b++)
#pragma unroll
            for (int c = 0; c < 4; c++) acc[a][b][c] = 0.f;

    const int nk = K / BK;
    uint32_t smA[NSTG], smB[NSTG];
#pragma unroll
    for (int s = 0; s < NSTG; s++) {
        smA[s] = (uint32_t)__cvta_generic_to_shared(smh + s * BM * SKS);
        smB[s] = (uint32_t)__cvta_generic_to_shared(smh + NSTG * BM * SKS + s * BN * SKS);
    }

    const int ldrow = tid >> 3, ldc8 = (tid & 7) << 3;
    const int grow[4] = { rowmap[ldrow], rowmap[ldrow + 32], rowmap[ldrow + 64], rowmap[ldrow + 96] };
    const uint32_t aoff = ((warp_m + (lane & 15)) * SKS + ((lane >> 4) << 3)) * 2;
    const uint32_t boff = ((warp_n + ((lane >> 4) & 1) * 8 + (lane & 7)) * SKS
                           + (((lane >> 3) & 1) << 3)) * 2;

#pragma unroll
    for (int s = 0; s < 2; s++) {
        int k0 = s * BK;
#pragma unroll
        for (int i = 0; i < 4; i++) {
            int row = ldrow + i * 32;
            const __half* src = (grow[i] >= 0) ? (A + (size_t)grow[i] * K + k0 + ldc8) : A;
            cp16(smA[s] + (row * SKS + ldc8) * 2, src, (grow[i] >= 0) ? 16 : 0);
        }
#pragma unroll
        for (int i = 0; i < 4; i++) {
            int row = ldrow + i * 32;
            cp16(smB[s] + (row * SKS + ldc8) * 2, B + (size_t)(n0 + row) * K + k0 + ldc8, 16);
        }
        cp_commit();
    }

    int cur = 0, pf = 2;
    for (int kt = 0; kt < nk; kt++) {
        cp_wait1();
        __syncthreads();
        if (kt + 2 < nk) {
            int k0 = (kt + 2) * BK;
#pragma unroll
            for (int i = 0; i < 4; i++) {
                int row = ldrow + i * 32;
                const __half* src = (grow[i] >= 0) ? (A + (size_t)grow[i] * K + k0 + ldc8) : A;
                cp16(smA[pf] + (row * SKS + ldc8) * 2, src, (grow[i] >= 0) ? 16 : 0);
            }
#pragma unroll
            for (int i = 0; i < 4; i++) {
                int row = ldrow + i * 32;
                cp16(smB[pf] + (row * SKS + ldc8) * 2, B + (size_t)(n0 + row) * K + k0 + ldc8, 16);
            }
        }
        cp_commit();

        const uint32_t sA = smA[cur], sB = smB[cur];
#pragma unroll
        for (int ks = 0; ks < 4; ks++) {
            const uint32_t kk2 = ks * 32;
            uint32_t af[4][4], bf[4][2];
#pragma unroll
            for (int mt = 0; mt < 4; mt++)
                ldm_x4(af[mt], sA + aoff + mt * 16 * SKS * 2 + kk2);
#pragma unroll
            for (int ntp = 0; ntp < 2; ntp++) {
                uint32_t tmp[4];
                ldm_x4(tmp, sB + boff + ntp * 16 * SKS * 2 + kk2);
                bf[2 * ntp][0] = tmp[0]; bf[2 * ntp][1] = tmp[1];
                bf[2 * ntp + 1][0] = tmp[2]; bf[2 * ntp + 1][1] = tmp[3];
            }
#pragma unroll
            for (int mt = 0; mt < 4; mt++)
#pragma unroll
                for (int nt = 0; nt < 4; nt++)
                    mma_h(acc[mt][nt], af[mt], bf[nt]);
        }
        cur = (cur + 1 == NSTG) ? 0 : cur + 1;
        pf = (pf + 1 == NSTG) ? 0 : pf + 1;
    }

#pragma unroll
    for (int mt = 0; mt < 4; mt++) {
        int r = warp_m + mt * 16 + g;
#pragma unroll
        for (int nt = 0; nt < 4; nt++) {
            int gc = n0 + warp_n + nt * 8 + tig * 2;
            if (m0 + r < cnt)
                *(__half2*)(Ch + (size_t)(start + m0 + r) * N + gc) =
                    __floats2half2_rn(acc[mt][nt][0], acc[mt][nt][1]);
            if (m0 + r + 8 < cnt)
                *(__half2*)(Ch + (size_t)(start + m0 + r + 8) * N + gc) =
                    __floats2half2_rn(acc[mt][nt][2], acc[mt][nt][3]);
        }
    }
}

// ---------------- fp16 flash attention ----------------
__global__ __launch_bounds__(256) void attn_h_kernel() {
    extern __shared__ __half smh[];
    __half* Qs  = smh;
    __half* Ksb = Qs + AQ * QST;
    __half* Vsb = Ksb + 2 * AK * KST;
    __half* Ps  = Vsb + 2 * AK * VST;

    const int h = blockIdx.y;
    const int qb = gridDim.x - 1 - blockIdx.x;
    const int q0 = qb * AQ;
    const int tid = threadIdx.x;
    const int warp = tid >> 5, lane = tid & 31;
    const int g = lane >> 2, tig = lane & 3;
    const int row0 = warp * 16 + g;
    const int qi0 = q0 + row0, qi1 = qi0 + 8;

    uint32_t smK[2], smV[2];
    smK[0] = (uint32_t)__cvta_generic_to_shared(Ksb);
    smK[1] = (uint32_t)__cvta_generic_to_shared(Ksb + AK * KST);
    smV[0] = (uint32_t)__cvta_generic_to_shared(Vsb);
    smV[1] = (uint32_t)__cvta_generic_to_shared(Vsb + AK * VST);
    const uint32_t smQ = (uint32_t)__cvta_generic_to_shared(Qs);
    const uint32_t smP = (uint32_t)__cvta_generic_to_shared(Ps);

    const uint32_t qoff = smQ + ((warp * 16 + (lane & 15)) * QST + ((lane >> 4) << 3)) * 2;
    const uint32_t koff = ((((lane >> 4) & 1) * 8 + (lane & 7)) * KST
                            + (((lane >> 3) & 1) << 3)) * 2;
    const uint32_t poff = smP + ((warp * 16 + (lane & 15)) * PST + ((lane >> 4) << 3)) * 2;
    const uint32_t voff = ((lane & 15) * VST + ((lane >> 4) & 1) * 8) * 2;

#pragma unroll
    for (int i = 0; i < 12; i++) {
        int idx = tid + i * 256;
        int r = idx / 24, c = (idx % 24) * 8;
        *(float4*)(Qs + r * QST + c) =
            *(const float4*)(a_q + ((size_t)(q0 + r) * NHEAD + h) * DQK + c);
    }

    float acc[16][4];
#pragma unroll
    for (int n = 0; n < 16; n++)
#pragma unroll
        for (int c = 0; c < 4; c++) acc[n][c] = 0.f;
    float m0 = -1e30f, m1 = -1e30f, l0 = 0.f, l1 = 0.f;
    const float scale = 0.07216878364870323f;

    const int ntiles = qb * 2 + 2;

    {
#pragma unroll
        for (int i = 0; i < 6; i++) {
            int idx = tid + i * 256;
            int r = idx / 24, c = (idx % 24) * 8;
            cp16(smK[0] + (r * KST + c) * 2,
                 a_kv + ((size_t)r * NHEAD + h) * (DQK + DV) + c, 16);
        }
#pragma unroll
        for (int i = 0; i < 4; i++) {
            int idx = tid + i * 256;
            int r = idx >> 4, c = (idx & 15) * 8;
            cp16(smV[0] + (r * VST + c) * 2,
                 a_kv + ((size_t)r * NHEAD + h) * (DQK + DV) + DQK + c, 16);
        }
        cp_commit();
    }

    for (int tile = 0; tile < ntiles; tile++) {
        const int cur = tile & 1, nb = cur ^ 1;
        __syncthreads();
        if (tile + 1 < ntiles) {
            int t1 = (tile + 1) * AK;
#pragma unroll
            for (int i = 0; i < 6; i++) {
                int idx = tid + i * 256;
                int r = idx / 24, c = (idx % 24) * 8;
                cp16(smK[nb] + (r * KST + c) * 2,
                     a_kv + ((size_t)(t1 + r) * NHEAD + h) * (DQK + DV) + c, 16);
            }
#pragma unroll
            for (int i = 0; i < 4; i++) {
                int idx = tid + i * 256;
                int r = idx >> 4, c = (idx & 15) * 8;
                cp16(smV[nb] + (r * VST + c) * 2,
                     a_kv + ((size_t)(t1 + r) * NHEAD + h) * (DQK + DV) + DQK + c, 16);
            }
            cp_commit();
            cp_wait1();
        } else {
            cp_wait0();
        }
        __syncthreads();

        const int t0 = tile * AK;
        float s[8][4];
#pragma unroll
        for (int n = 0; n < 8; n++)
#pragma unroll
            for (int c = 0; c < 4; c++) s[n][c] = 0.f;
#pragma unroll
        for (int ks = 0; ks < 12; ks++) {
            const uint32_t kk2 = ks * 32;
            uint32_t af[4];
            ldm_x4(af, qoff + kk2);
#pragma unroll
            for (int ntp = 0; ntp < 4; ntp++) {
                uint32_t tmp[4];
                ldm_x4(tmp, smK[cur] + koff + ntp * 16 * KST * 2 + kk2);
                mma_h(s[2 * ntp],     af, tmp);
                mma_h(s[2 * ntp + 1], af, tmp + 2);
            }
        }

        const bool domask = (t0 + AK - 1 > q0);
#pragma unroll
        for (int nt = 0; nt < 8; nt++) {
#pragma unroll
            for (int c = 0; c < 4; c++) s[nt][c] *= scale;
            if (domask) {
                int kj = t0 + nt * 8 + tig * 2;
                if (kj > qi0)     s[nt][0] = -1e30f;
                if (kj + 1 > qi0) s[nt][1] = -1e30f;
                if (kj > qi1)     s[nt][2] = -1e30f;
                if (kj + 1 > qi1) s[nt][3] = -1e30f;
            }
        }

        float mx0 = -1e30f, mx1 = -1e30f;
#pragma unroll
        for (int nt = 0; nt < 8; nt++) {
            mx0 = fmaxf(mx0, fmaxf(s[nt][0], s[nt][1]));
            mx1 = fmaxf(mx1, fmaxf(s[nt][2], s[nt][3]));
        }
        mx0 = fmaxf(mx0, __shfl_xor_sync(0xffffffffu, mx0, 1));
        mx0 = fmaxf(mx0, __shfl_xor_sync(0xffffffffu, mx0, 2));
        mx1 = fmaxf(mx1, __shfl_xor_sync(0xffffffffu, mx1, 1));
        mx1 = fmaxf(mx1, __shfl_xor_sync(0xffffffffu, mx1, 2));

        float mn0 = fmaxf(m0, mx0), mn1 = fmaxf(m1, mx1);
        float cf0 = __expf(m0 - mn0), cf1 = __expf(m1 - mn1);
        m0 = mn0; m1 = mn1;

        float sum0 = 0.f, sum1 = 0.f;
#pragma unroll
        for (int nt = 0; nt < 8; nt++) {
            float p0 = __expf(s[nt][0] - m0);
            float p1 = __expf(s[nt][1] - m0);
            float p2 = __expf(s[nt][2] - m1);
            float p3 = __expf(s[nt][3] - m1);
            sum0 += p0 + p1; sum1 += p2 + p3;
            *(__half2*)(Ps + row0 * PST + nt * 8 + tig * 2) = __floats2half2_rn(p0, p1);
            *(__half2*)(Ps + (row0 + 8) * PST + nt * 8 + tig * 2) = __floats2half2_rn(p2, p3);
        }
        sum0 += __shfl_xor_sync(0xffffffffu, sum0, 1);
        sum0 += __shfl_xor_sync(0xffffffffu, sum0, 2);
        sum1 += __shfl_xor_sync(0xffffffffu, sum1, 1);
        sum1 += __shfl_xor_sync(0xffffffffu, sum1, 2);
        l0 = l0 * cf0 + sum0;
        l1 = l1 * cf1 + sum1;
#pragma unroll
        for (int nt = 0; nt < 16; nt++) {
            acc[nt][0] *= cf0; acc[nt][1] *= cf0;
            acc[nt][2] *= cf1; acc[nt][3] *= cf1;
        }
        __syncwarp();

#pragma unroll
        for (int ks = 0; ks < 4; ks++) {
            uint32_t af[4];
            ldm_x4(af, poff + ks * 32);
            const uint32_t vbase = smV[cur] + voff + (uint32_t)(ks * 16) * VST * 2;
#pragma unroll
            for (int ntp = 0; ntp < 8; ntp++) {
                uint32_t tmp[4];
                ldm_x4_t(tmp, vbase + ntp * 16 * 2);
                mma_h(acc[2 * ntp],     af, tmp);
                mma_h(acc[2 * ntp + 1], af, tmp + 2);
            }
        }
    }

    float inv0 = 1.0f / l0, inv1 = 1.0f / l1;
#pragma unroll
    for (int nt = 0; nt < 16; nt++) {
        int col = h * DV + nt * 8 + tig * 2;
        *(__half2*)(a_ctx + (size_t)qi0 * (NHEAD * DV) + col) =
            __floats2half2_rn(acc[nt][0] * inv0, acc[nt][1] * inv0);
        *(__half2*)(a_ctx + (size_t)qi1 * (NHEAD * DV) + col) =
            __floats2half2_rn(acc[nt][2] * inv1, acc[nt][3] * inv1);
    }
}

// ---------------- RMSNorm: one-pass, float4, register-cached ----------------
__global__ void rmsnorm_h(const float* in, const float* w, __half* out, float* outf, int D) {
    int t = blockIdx.x;
    const float4* row = (const float4*)(in + (size_t)t * D);
    const int n4 = D >> 2;
    float4 cache[2];
    int cnt = 0;
    float ss = 0.f;
    for (int i = threadIdx.x; i < n4; i += 256) {
        float4 v = row[i];
        cache[cnt++] = v;
        ss += v.x * v.x + v.y * v.y + v.z * v.z + v.w * v.w;
    }
    __shared__ float sred[32];
    for (int o = 16; o > 0; o >>= 1) ss += __shfl_down_sync(0xffffffffu, ss, o);
    int lane = threadIdx.x & 31, warp = threadIdx.x >> 5;
    if (lane == 0) sred[warp] = ss;
    __syncthreads();
    if (threadIdx.x == 0) {
        float tot = 0.f;
        for (int i = 0; i < 8; i++) tot += sred[i];
        sred[0] = 1.0f / sqrtf(tot / (float)D + 1e-6f);
    }
    __syncthreads();
    float scale = sred[0];
    cnt = 0;
    for (int i = threadIdx.x; i < n4; i += 256) {
        float4 v = cache[cnt++];
        const float4 wv = *(const float4*)(w + 4 * i);
        float r0 = v.x * scale * wv.x, r1 = v.y * scale * wv.y;
        float r2 = v.z * scale * wv.z, r3 = v.w * scale * wv.w;
        __half2 p[2];
        p[0] = __floats2half2_rn(r0, r1);
        p[1] = __floats2half2_rn(r2, r3);
        *(float2*)(out + (size_t)t * D + 4 * i) = *(float2*)p;
        if (outf) *(float4*)(outf + (size_t)t * D + 4 * i) = make_float4(r0, r1, r2, r3);
    }
}

// ---------------- RoPE ----------------
__global__ void rope_h_kernel() {
    int idx = blockIdx.x * blockDim.x + threadIdx.x;
    int total = SEQ * NHEAD * (ROPED / 2);
    if (idx >= total) return;
    int i = idx & 31;
    int h = (idx >> 5) & (NHEAD - 1);
    int t = idx >> 9;
    float inv_freq = powf(10000.0f, -(float)(2 * i) / (float)ROPED);
    float f = (float)t * inv_freq;
    float c = cosf(f), s = sinf(f);
    __half* qp = a_q + ((size_t)t * NHEAD + h) * DQK + NOPE;
    float x1 = __half2float(qp[i]), x2 = __half2float(qp[i + 32]);
    qp[i] = __float2half(x1 * c - x2 * s);
    qp[i + 32] = __float2half(x2 * c + x1 * s);
    __half* kp = a_kv + ((size_t)t * NHEAD + h) * (DQK + DV) + NOPE;
    x1 = __half2float(kp[i]); x2 = __half2float(kp[i + 32]);
    kp[i] = __float2half(x1 * c - x2 * s);
    kp[i + 32] = __float2half(x2 * c + x1 * s);
}

// ---------------- Router (fp32 h2) — also zeroes expert counters ----------------
__global__ void router_kernel(const float* __restrict__ rw, const float* __restrict__ rb) {
    int t = blockIdx.x;
    if (t == 0 && threadIdx.x < NEXP) { g_cnt[threadIdx.x] = 0; g_fill[threadIdx.x] = 0; }
    float part[NEXP];
#pragma unroll
    for (int e = 0; e < NEXP; e++) part[e] = 0.f;
    for (int hh = threadIdx.x; hh < HDIM; hh += 128) {
        float xv = g_h2f[(size_t)t * HDIM + hh];
#pragma unroll
        for (int e = 0; e < NEXP; e++) part[e] += xv * rw[(size_t)e * HDIM + hh];
    }
    __shared__ float sred[4][NEXP];
#pragma unroll
    for (int e = 0; e < NEXP; e++)
        for (int o = 16; o > 0; o >>= 1) part[e] += __shfl_down_sync(0xffffffffu, part[e], o);
    int lane = threadIdx.x & 31, warp = threadIdx.x >> 5;
    if (lane == 0)
#pragma unroll
        for (int e = 0; e < NEXP; e++) sred[warp][e] = part[e];
    __syncthreads();
    if (threadIdx.x < NEXP) {
        int e = threadIdx.x;
        g_logits[t * NEXP + e] = sred[0][e] + sred[1][e] + sred[2][e] + sred[3][e] + rb[e];
    }
}

__global__ void topk_kernel() {
    int t = blockIdx.x * blockDim.x + threadIdx.x;
    if (t >= SEQ) return;
    float p[NEXP];
#pragma unroll
    for (int e = 0; e < NEXP; e++) p[e] = 1.0f / (1.0f + expf(-g_logits[t * NEXP + e]));
    float vals[TOPK]; int ids[TOPK];
    float sum = 0.f;
#pragma unroll
    for (int k = 0; k < TOPK; k++) {
        float best = -1e30f; int bi = 0;
#pragma unroll
        for (int e = 0; e < NEXP; e++)
            if (p[e] > best) { best = p[e]; bi = e; }
        vals[k] = best; ids[k] = bi; p[bi] = -1e30f; sum += best;
    }
    float w = 2.5f / (sum + 1e-9f);
#pragma unroll
    for (int k = 0; k < TOPK; k++) {
        g_wtop[t * TOPK + k] = vals[k] * w;
        g_topi[t * TOPK + k] = ids[k];
        atomicAdd(&g_cnt[ids[k]], 1);
    }
}

__global__ void offsets_kernel() {
    if (threadIdx.x == 0) {
        g_off[0] = 0;
        for (int e = 0; e < NEXP; e++) g_off[e + 1] = g_off[e] + g_cnt[e];
    }
}

__global__ void scatter_kernel() {
    int t = blockIdx.x * blockDim.x + threadIdx.x;
    if (t >= SEQ) return;
#pragma unroll
    for (int k = 0; k < TOPK; k++) {
        int e = g_topi[t * TOPK + k];
        int pos = atomicAdd(&g_fill[e], 1);
        int slot = g_off[e] + pos;
        g_slot[t * TOPK + k] = slot;
        g_tok[slot] = t;
    }
}

// ---------------- SiLU(a)*b, fp16 ----------------
__global__ void act_h_kernel(__half2* a, const __half2* b, size_t n2) {
    size_t i = (size_t)blockIdx.x * blockDim.x + threadIdx.x;
    if (i >= n2) return;
    float2 gg = __half22float2(a[i]);
    float2 uu = __half22float2(b[i]);
    gg.x = gg.x / (1.0f + expf(-gg.x)) * uu.x;
    gg.y = gg.y / (1.0f + expf(-gg.y)) * uu.y;
    a[i] = __floats2half2_rn(gg.x, gg.y);
}

// ---------------- Final combine (float4) ----------------
__global__ void combine_kernel(float* out) {
    int t = blockIdx.x;
    float w[TOPK]; int s[TOPK];
#pragma unroll
    for (int k = 0; k < TOPK; k++) { w[k] = g_wtop[t * TOPK + k]; s[k] = g_slot[t * TOPK + k]; }
    for (int i = threadIdx.x; i < HDIM / 4; i += 256) {
        float4 v = *(const float4*)(g_xmid + (size_t)t * HDIM + 4 * i);
        float4 sh = *(const float4*)(g_shr + (size_t)t * HDIM + 4 * i);
        v.x += sh.x; v.y += sh.y; v.z += sh.z; v.w += sh.w;
#pragma unroll
        for (int k = 0; k < TOPK; k++) {
            float2 d01 = __half22float2(*(const __half2*)(a_down + (size_t)s[k] * HDIM + 4 * i));
            float2 d23 = __half22float2(*(const __half2*)(a_down + (size_t)s[k] * HDIM + 4 * i + 2));
            v.x += w[k] * d01.x; v.y += w[k] * d01.y;
            v.z += w[k] * d23.x; v.w += w[k] * d23.y;
        }
        *(float4*)(out + (size_t)t * HDIM + 4 * i) = v;
    }
}

// ---------------- host ----------------
static float* symf(const void* sym) { void* p = nullptr; cudaGetSymbolAddress(&p, sym); return (float*)p; }
static __half* symh(const void* sym) { void* p = nullptr; cudaGetSymbolAddress(&p, sym); return (__half*)p; }
static int*   symi(const void* sym) { void* p = nullptr; cudaGetSymbolAddress(&p, sym); return (int*)p; }

static void launch_conv_batch(const float* const* ins, __half* const* outs,
                              const size_t* ns, int n, cudaStream_t stream) {
    ConvBatch cb;
    int acc = 0;
    for (int s = 0; s < NSEG; s++) {
        if (s < n) {
            cb.in[s] = (const float4*)ins[s];
            cb.out[s] = outs[s];
            cb.start[s] = acc;
            acc += (int)(ns[s] / 4);
        } else {
            cb.in[s] = (const float4*)ins[n - 1];
            cb.out[s] = outs[n - 1];
            cb.start[s] = 0x7fffffff;
        }
    }
    cb.start[NSEG] = acc;
    conv_batch_kernel<<<(acc + 255) / 256, 256, 0, stream>>>(cb);
}

extern "C" void kernel_launch(void* const* d_in, const int* in_sizes, int n_in,
                              void* d_out, int out_size)
{
    const float* x      = (const float*)d_in[0];
    const float* ln1_w  = (const float*)d_in[2];
    const float* ln2_w  = (const float*)d_in[3];
    const float* q_a_w  = (const float*)d_in[4];
    const float* q_a_ln = (const float*)d_in[5];
    const float* q_b_w  = (const float*)d_in[6];
    const float* kv_a_w = (const float*)d_in[7];
    const float* kv_a_ln= (const float*)d_in[8];
    const float* kv_b_w = (const float*)d_in[9];
    const float* o_w    = (const float*)d_in[10];
    const float* rout_w = (const float*)d_in[11];
    const float* rout_b = (const float*)d_in[12];
    const float* gate_w = (const float*)d_in[13];
    const float* up_w   = (const float*)d_in[14];
    const float* down_w = (const float*)d_in[15];
    const float* sg_w   = (const float*)d_in[16];
    const float* su_w   = (const float*)d_in[17];
    const float* sd_w   = (const float*)d_in[18];
    float* out = (float*)d_out;

    __half* wqa  = symh(w_qa);   __half* wkva = symh(w_kva);
    __half* wqb  = symh(w_qb);   __half* wkvb = symh(w_kvb);
    __half* wo   = symh(w_o);
    __half* wg   = symh(w_gate); __half* wu   = symh(w_up);  __half* wd = symh(w_down);
    __half* wsg  = symh(w_sg);   __half* wsu  = symh(w_su);  __half* wsd = symh(w_sd);

    __half* h1h  = symh(a_h1);
    __half* qah  = symh(a_qa);   __half* kvah = symh(a_kva);
    __half* qh   = symh(a_q);    __half* kvh  = symh(a_kv);
    __half* ctxh = symh(a_ctx);  __half* h2h  = symh(a_h2);
    __half* gth  = symh(a_gate); __half* uph  = symh(a_up);
    __half* dnh  = symh(a_down);
    __half* sgh  = symh(a_sg);   __half* suh  = symh(a_su);

    float* qaf  = symf(g_qa);   float* kvaf = symf(g_kva);
    float* xmid = symf(g_xmid); float* h2f  = symf(g_h2f);
    float* shr  = symf(g_shr);
    int* tok = symi(g_tok);     int* off = symi(g_off);

    cudaFuncSetAttribute(gemm_h, cudaFuncAttributeMaxDynamicSharedMemorySize, GSMEM);
    cudaFuncSetAttribute(gemm_h_moe, cudaFuncAttributeMaxDynamicSharedMemorySize, GSMEM);
    cudaFuncSetAttribute(attn_h_kernel, cudaFuncAttributeMaxDynamicSharedMemorySize, ATTN_SMEM);

    // ---- stream fork: MoE/shared-expert weight conversion overlaps attention branch ----
    cudaStream_t s2;
    cudaStreamCreateWithFlags(&s2, cudaStreamNonBlocking);
    cudaEvent_t evFork, evJoin;
    cudaEventCreateWithFlags(&evFork, cudaEventDisableTiming);
    cudaEventCreateWithFlags(&evJoin, cudaEventDisableTiming);

    cudaEventRecord(evFork, 0);
    cudaStreamWaitEvent(s2, evFork, 0);
    {
        const float* ins2[6] = { gate_w, up_w, down_w, sg_w, su_w, sd_w };
        __half* outs2[6] = { wg, wu, wd, wsg, wsu, wsd };
        size_t ns2[6] = { (size_t)NEXP * MINT * HDIM, (size_t)NEXP * MINT * HDIM,
                          (size_t)NEXP * HDIM * MINT,
                          (size_t)MINT * HDIM, (size_t)MINT * HDIM, (size_t)HDIM * MINT };
        launch_conv_batch(ins2, outs2, ns2, 6, s2);
    }
    cudaEventRecord(evJoin, s2);

    // attention weights on main stream
    {
        const float* ins1[5] = { q_a_w, kv_a_w, q_b_w, kv_b_w, o_w };
        __half* outs1[5] = { wqa, wkva, wqb, wkvb, wo };
        size_t ns1[5] = { (size_t)QRNK * HDIM, (size_t)KVRNK * HDIM,
                          (size_t)NHEAD * DQK * QRNK, (size_t)NHEAD * (DQK + DV) * KVRNK,
                          (size_t)HDIM * NHEAD * DV };
        launch_conv_batch(ins1, outs1, ns1, 5, 0);
    }

    // ---- attention branch ----
    rmsnorm_h<<<SEQ, 256>>>(x, ln1_w, h1h, nullptr, HDIM);
    gemm_h<<<dim3((QRNK + KVRNK) / BN, SEQ / BM), 256, GSMEM>>>(
        h1h, wqa, qaf, nullptr, nullptr, QRNK, HDIM,
        h1h, wkva, kvaf, nullptr, KVRNK, HDIM, SEQ);
    rmsnorm_h<<<SEQ, 256>>>(qaf, q_a_ln, qah, nullptr, QRNK);
    rmsnorm_h<<<SEQ, 256>>>(kvaf, kv_a_ln, kvah, nullptr, KVRNK);
    gemm_h<<<dim3((NHEAD * DQK + NHEAD * (DQK + DV)) / BN, SEQ / BM), 256, GSMEM>>>(
        qah, wqb, nullptr, qh, nullptr, NHEAD * DQK, QRNK,
        kvah, wkvb, nullptr, kvh, NHEAD * (DQK + DV), KVRNK, SEQ);
    rope_h_kernel<<<(SEQ * NHEAD * (ROPED / 2) + 255) / 256, 256>>>();
    attn_h_kernel<<<dim3(SEQ / AQ, NHEAD), 256, ATTN_SMEM>>>();
    gemm_h<<<dim3(HDIM / BN, SEQ / BM), 256, GSMEM>>>(
        ctxh, wo, xmid, nullptr, x, HDIM, NHEAD * DV,
        nullptr, nullptr, nullptr, nullptr, 0, BK, SEQ);

    // ---- MoE branch ----
    rmsnorm_h<<<SEQ, 256>>>(xmid, ln2_w, h2h, h2f, HDIM);
    router_kernel<<<SEQ, 128>>>(rout_w, rout_b);
    topk_kernel<<<SEQ / 256, 256>>>();
    offsets_kernel<<<1, 1>>>();
    scatter_kernel<<<SEQ / 256, 256>>>();

    // join: MoE weights must be converted before expert GEMMs
    cudaStreamWaitEvent(0, evJoin, 0);

    gemm_h_moe<<<dim3(2 * MINT / BN, SEQ / BM, NEXP), 256, GSMEM>>>(
        h2h, tok, wg, gth, MINT, wu, uph, MINT, (size_t)MINT * HDIM, HDIM, off);
    act_h_kernel<<<(unsigned)(((size_t)NSLOT * MINT / 2 + 255) / 256), 256>>>(
        (__half2*)gth, (const __half2*)uph, (size_t)NSLOT * MINT / 2);
    gemm_h_moe<<<dim3(HDIM / BN, SEQ / BM, NEXP), 256, GSMEM>>>(
        gth, nullptr, wd, dnh, HDIM, nullptr, nullptr, 0, (size_t)HDIM * MINT, MINT, off);

    // shared expert
    gemm_h<<<dim3(2 * MINT / BN, SEQ / BM), 256, GSMEM>>>(
        h2h, wsg, nullptr, sgh, nullptr, MINT, HDIM,
        h2h, wsu, nullptr, suh, MINT, HDIM, SEQ);
    act_h_kernel<<<(unsigned)(((size_t)SEQ * MINT / 2 + 255) / 256), 256>>>(
        (__half2*)sgh, (const __half2*)suh, (size_t)SEQ * MINT / 2);
    gemm_h<<<dim3(HDIM / BN, SEQ / BM), 256, GSMEM>>>(
        sgh, wsd, shr, nullptr, nullptr, HDIM, MINT,
        nullptr, nullptr, nullptr, nullptr, 0, BK, SEQ);

    combine_kernel<<<SEQ, 256>>>(out);
}

// round 13
// speedup vs baseline: 1.3458x; 1.3458x over previous
#include <cuda_runtime.h>
#include <cuda_fp16.h>
#include <math.h>
#include <stdint.h>

// ---------------- problem constants ----------------
#define SEQ   2048
#define HDIM  2048
#define NHEAD 16
#define DQK   192
#define DV    128
#define NOPE  128
#define ROPED 64
#define QRNK  768
#define KVRNK 512
#define NEXP  16
#define TOPK  4
#define MINT  1024
#define NSLOT (SEQ*TOPK)

// GEMM tiling (fp16, m16n8k16), 3-stage pipeline
#define BM 128
#define BN 128
#define BK 64
#define SKS 72
#define NSTG 3
#define GSMEM (NSTG*(BM+BN)*SKS*2)

// attention tiling (double-buffered K/V)
#define AQ 128
#define AK 64
#define QST 200
#define KST 200
#define VST 136
#define PST 72
#define ATTN_SMEM ((AQ*QST + 2*AK*KST + 2*AK*VST + AQ*PST)*2)

// ---------------- fp32 scratch ----------------
__device__ float g_qa[SEQ*QRNK];
__device__ float g_kva[SEQ*KVRNK];
__device__ float g_xmid[SEQ*HDIM];
__device__ float g_h2f[SEQ*HDIM];
__device__ float g_shr[SEQ*HDIM];
__device__ float g_logits[SEQ*NEXP];
__device__ float g_wtop[SEQ*TOPK];
__device__ int   g_topi[SEQ*TOPK];
__device__ int   g_slot[SEQ*TOPK];
__device__ int   g_cnt[NEXP];
__device__ int   g_off[NEXP+1];
__device__ int   g_fill[NEXP];
__device__ int   g_tok[NSLOT];

// ---------------- fp16 weights ----------------
__device__ __half w_qa[QRNK*HDIM];
__device__ __half w_kva[KVRNK*HDIM];
__device__ __half w_qb[NHEAD*DQK*QRNK];
__device__ __half w_kvb[NHEAD*(DQK+DV)*KVRNK];
__device__ __half w_o[HDIM*NHEAD*DV];
__device__ __half w_gate[(size_t)NEXP*MINT*HDIM];
__device__ __half w_up[(size_t)NEXP*MINT*HDIM];
__device__ __half w_down[(size_t)NEXP*HDIM*MINT];
__device__ __half w_sg[MINT*HDIM];
__device__ __half w_su[MINT*HDIM];
__device__ __half w_sd[HDIM*MINT];

// ---------------- fp16 activations ----------------
__device__ __half a_h1[SEQ*HDIM];
__device__ __half a_qa[SEQ*QRNK];
__device__ __half a_kva[SEQ*KVRNK];
__device__ __half a_q[SEQ*NHEAD*DQK];
__device__ __half a_kv[SEQ*NHEAD*(DQK+DV)];
__device__ __half a_ctx[SEQ*NHEAD*DV];
__device__ __half a_h2[SEQ*HDIM];
__device__ __half a_gate[(size_t)NSLOT*MINT];
__device__ __half a_up[(size_t)NSLOT*MINT];
__device__ __half a_down[(size_t)NSLOT*HDIM];
__device__ __half a_sg[SEQ*MINT];
__device__ __half a_su[SEQ*MINT];

// ---------------- helpers ----------------
__device__ __forceinline__ void cp16(uint32_t dst, const void* src, int szbytes) {
    asm volatile("cp.async.cg.shared.global [%0], [%1], 16, %2;\n"
                 :: "r"(dst), "l"(src), "r"(szbytes));
}
__device__ __forceinline__ void cp_commit() { asm volatile("cp.async.commit_group;\n"); }
__device__ __forceinline__ void cp_wait0()  { asm volatile("cp.async.wait_group 0;\n"); }
__device__ __forceinline__ void cp_wait1()  { asm volatile("cp.async.wait_group 1;\n"); }

__device__ __forceinline__ void mma_h(float* c, const uint32_t* a, const uint32_t* b) {
    asm volatile(
        "mma.sync.aligned.m16n8k16.row.col.f32.f16.f16.f32 "
        "{%0,%1,%2,%3}, {%4,%5,%6,%7}, {%8,%9}, {%0,%1,%2,%3};\n"
        : "+f"(c[0]), "+f"(c[1]), "+f"(c[2]), "+f"(c[3])
        : "r"(a[0]), "r"(a[1]), "r"(a[2]), "r"(a[3]), "r"(b[0]), "r"(b[1]));
}
__device__ __forceinline__ void ldm_x4(uint32_t* r, uint32_t addr) {
    asm volatile("ldmatrix.sync.aligned.m8n8.x4.shared.b16 {%0,%1,%2,%3}, [%4];"
                 : "=r"(r[0]), "=r"(r[1]), "=r"(r[2]), "=r"(r[3]) : "r"(addr));
}
__device__ __forceinline__ void ldm_x4_t(uint32_t* r, uint32_t addr) {
    asm volatile("ldmatrix.sync.aligned.m8n8.x4.trans.shared.b16 {%0,%1,%2,%3}, [%4];"
                 : "=r"(r[0]), "=r"(r[1]), "=r"(r[2]), "=r"(r[3]) : "r"(addr));
}

// ---------------- batched fp32 -> fp16 convert (all weights, one launch) ----------------
#define NSEG 11
struct ConvBatch {
    const float4* in[NSEG];
    __half* out[NSEG];
    int start[NSEG + 1];
};
__global__ void conv_batch_kernel(ConvBatch cb) {
    int i = blockIdx.x * blockDim.x + threadIdx.x;
    if (i >= cb.start[NSEG]) return;
    int seg = 0;
#pragma unroll
    for (int s = 1; s < NSEG; s++) seg += (i >= cb.start[s]);
    int local = i - cb.start[seg];
    float4 v = __ldcs(cb.in[seg] + local);
    __half2 p[2];
    p[0] = __floats2half2_rn(v.x, v.y);
    p[1] = __floats2half2_rn(v.z, v.w);
    __stcs((float2*)(cb.out[seg] + (size_t)local * 4), *(float2*)p);
}

// ---------------- fp16 tensor-core GEMM (dual segment, 3-stage) ----------------
__global__ __launch_bounds__(256, 2) void gemm_h(
    const __half* __restrict__ A1,
    const __half* __restrict__ B1, float* C1, __half* C1h, const float* add1, int N1, int K1,
    const __half* __restrict__ A2,
    const __half* __restrict__ B2, float* C2, __half* C2h, int N2, int K2,
    int M)
{
    extern __shared__ __half smh[];

    int n0 = blockIdx.x * BN;
    const __half *A, *B; float* C; __half* Ch; const float* addsrc; int N, K;
    if (n0 < N1) { A = A1; B = B1; C = C1; Ch = C1h; addsrc = add1; N = N1; K = K1; }
    else { n0 -= N1; A = A2; B = B2; C = C2; Ch = C2h; addsrc = nullptr; N = N2; K = K2; }

    const int tid = threadIdx.x;
    const int warp = tid >> 5, lane = tid & 31;
    const int g = lane >> 2, tig = lane & 3;
    const int warp_m = (warp & 1) * 64, warp_n = (warp >> 1) * 32;
    const int m0 = blockIdx.y * BM;

    float acc[4][4][4];
#pragma unroll
    for (int a = 0; a < 4; a++)
#pragma unroll
        for (int b = 0; b < 4; b++)
#pragma unroll
            for (int c = 0; c < 4; c++) acc[a][b][c] = 0.f;

    const int nk = K / BK;
    uint32_t smA[NSTG], smB[NSTG];
#pragma unroll
    for (int s = 0; s < NSTG; s++) {
        smA[s] = (uint32_t)__cvta_generic_to_shared(smh + s * BM * SKS);
        smB[s] = (uint32_t)__cvta_generic_to_shared(smh + NSTG * BM * SKS + s * BN * SKS);
    }

    const int ldrow = tid >> 3, ldc8 = (tid & 7) << 3;
    const uint32_t aoff = ((warp_m + (lane & 15)) * SKS + ((lane >> 4) << 3)) * 2;
    const uint32_t boff = ((warp_n + ((lane >> 4) & 1) * 8 + (lane & 7)) * SKS
                           + (((lane >> 3) & 1) << 3)) * 2;

#pragma unroll
    for (int s = 0; s < 2; s++) {
        int k0 = s * BK;
#pragma unroll
        for (int i = 0; i < 4; i++) {
            int row = ldrow + i * 32;
            cp16(smA[s] + (row * SKS + ldc8) * 2, A + (size_t)(m0 + row) * K + k0 + ldc8, 16);
        }
#pragma unroll
        for (int i = 0; i < 4; i++) {
            int row = ldrow + i * 32;
            cp16(smB[s] + (row * SKS + ldc8) * 2, B + (size_t)(n0 + row) * K + k0 + ldc8, 16);
        }
        cp_commit();
    }

    int cur = 0, pf = 2;
    for (int kt = 0; kt < nk; kt++) {
        cp_wait1();
        __syncthreads();
        if (kt + 2 < nk) {
            int k0 = (kt + 2) * BK;
#pragma unroll
            for (int i = 0; i < 4; i++) {
                int row = ldrow + i * 32;
                cp16(smA[pf] + (row * SKS + ldc8) * 2, A + (size_t)(m0 + row) * K + k0 + ldc8, 16);
            }
#pragma unroll
            for (int i = 0; i < 4; i++) {
                int row = ldrow + i * 32;
                cp16(smB[pf] + (row * SKS + ldc8) * 2, B + (size_t)(n0 + row) * K + k0 + ldc8, 16);
            }
        }
        cp_commit();

        const uint32_t sA = smA[cur], sB = smB[cur];
#pragma unroll
        for (int ks = 0; ks < 4; ks++) {
            const uint32_t kk2 = ks * 32;
            uint32_t af[4][4], bf[4][2];
#pragma unroll
            for (int mt = 0; mt < 4; mt++)
                ldm_x4(af[mt], sA + aoff + mt * 16 * SKS * 2 + kk2);
#pragma unroll
            for (int ntp = 0; ntp < 2; ntp++) {
                uint32_t tmp[4];
                ldm_x4(tmp, sB + boff + ntp * 16 * SKS * 2 + kk2);
                bf[2 * ntp][0] = tmp[0]; bf[2 * ntp][1] = tmp[1];
                bf[2 * ntp + 1][0] = tmp[2]; bf[2 * ntp + 1][1] = tmp[3];
            }
#pragma unroll
            for (int mt = 0; mt < 4; mt++)
#pragma unroll
                for (int nt = 0; nt < 4; nt++)
                    mma_h(acc[mt][nt], af[mt], bf[nt]);
        }
        cur = (cur + 1 == NSTG) ? 0 : cur + 1;
        pf = (pf + 1 == NSTG) ? 0 : pf + 1;
    }

#pragma unroll
    for (int mt = 0; mt < 4; mt++) {
        int r0 = m0 + warp_m + mt * 16 + g;
#pragma unroll
        for (int nt = 0; nt < 4; nt++) {
            int gc = n0 + warp_n + nt * 8 + tig * 2;
            float v0 = acc[mt][nt][0], v1 = acc[mt][nt][1];
            float v2 = acc[mt][nt][2], v3 = acc[mt][nt][3];
            if (addsrc) {
                v0 += addsrc[(size_t)r0 * N + gc];
                v1 += addsrc[(size_t)r0 * N + gc + 1];
                v2 += addsrc[(size_t)(r0 + 8) * N + gc];
                v3 += addsrc[(size_t)(r0 + 8) * N + gc + 1];
            }
            if (C) {
                *(float2*)(C + (size_t)r0 * N + gc) = make_float2(v0, v1);
                *(float2*)(C + (size_t)(r0 + 8) * N + gc) = make_float2(v2, v3);
            }
            if (Ch) {
                *(__half2*)(Ch + (size_t)r0 * N + gc) = __floats2half2_rn(v0, v1);
                *(__half2*)(Ch + (size_t)(r0 + 8) * N + gc) = __floats2half2_rn(v2, v3);
            }
        }
    }
}

// ---------------- fp16 grouped MoE GEMM (dual-B, gathered A, 3-stage) ----------------
__global__ __launch_bounds__(256, 2) void gemm_h_moe(
    const __half* __restrict__ A, const int* __restrict__ gather,
    const __half* __restrict__ B1b, __half* C1h, int N1,
    const __half* __restrict__ B2b, __half* C2h, int N2,
    size_t strideB, int K, const int* __restrict__ off)
{
    const int e = blockIdx.z;
    const int start = off[e];
    const int cnt = off[e + 1] - start;
    const int m0 = blockIdx.y * BM;
    if (m0 >= cnt) return;

    int n0 = blockIdx.x * BN;
    const __half* B; __half* Ch; int N;
    if (n0 < N1) { B = B1b + (size_t)e * strideB; Ch = C1h; N = N1; }
    else { n0 -= N1; B = B2b + (size_t)e * strideB; Ch = C2h; N = N2; }

    extern __shared__ __half smh[];
    __shared__ int rowmap[BM];

    const int tid = threadIdx.x;
    if (tid < BM) {
        int r = m0 + tid;
        int gr = -1;
        if (r < cnt) gr = gather ? gather[start + r] : (start + r);
        rowmap[tid] = gr;
    }
    __syncthreads();

    const int warp = tid >> 5, lane = tid & 31;
    const int g = lane >> 2, tig = lane & 3;
    const int warp_m = (warp & 1) * 64, warp_n = (warp >> 1) * 32;

    float acc[4][4][4];
#pragma unroll
    for (int a = 0; a < 4; a++)
#pragma unroll
        for (int b = 0; b < 4; b++)
#pragma unroll
            for (int c = 0; c < 4; c++) acc[a][b][c] = 0.f;

    const int nk = K / BK;
    uint32_t smA[NSTG], smB[NSTG];
#pragma unroll
    for (int s = 0; s < NSTG; s++) {
        smA[s] = (uint32_t)__cvta_generic_to_shared(smh + s * BM * SKS);
        smB[s] = (uint32_t)__cvta_generic_to_shared(smh + NSTG * BM * SKS + s * BN * SKS);
    }

    const int ldrow = tid >> 3, ldc8 = (tid & 7) << 3;
    const int grow[4] = { rowmap[ldrow], rowmap[ldrow + 32], rowmap[ldrow + 64], rowmap[ldrow + 96] };
    const uint32_t aoff = ((warp_m + (lane & 15)) * SKS + ((lane >> 4) << 3)) * 2;
    const uint32_t boff = ((warp_n + ((lane >> 4) & 1) * 8 + (lane & 7)) * SKS
                           + (((lane >> 3) & 1) << 3)) * 2;

#pragma unroll
    for (int s = 0; s < 2; s++) {
        int k0 = s * BK;
#pragma unroll
        for (int i = 0; i < 4; i++) {
            int row = ldrow + i * 32;
            const __half* src = (grow[i] >= 0) ? (A + (size_t)grow[i] * K + k0 + ldc8) : A;
            cp16(smA[s] + (row * SKS + ldc8) * 2, src, (grow[i] >= 0) ? 16 : 0);
        }
#pragma unroll
        for (int i = 0; i < 4; i++) {
            int row = ldrow + i * 32;
            cp16(smB[s] + (row * SKS + ldc8) * 2, B + (size_t)(n0 + row) * K + k0 + ldc8, 16);
        }
        cp_commit();
    }

    int cur = 0, pf = 2;
    for (int kt = 0; kt < nk; kt++) {
        cp_wait1();
        __syncthreads();
        if (kt + 2 < nk) {
            int k0 = (kt + 2) * BK;
#pragma unroll
            for (int i = 0; i < 4; i++) {
                int row = ldrow + i * 32;
                const __half* src = (grow[i] >= 0) ? (A + (size_t)grow[i] * K + k0 + ldc8) : A;
                cp16(smA[pf] + (row * SKS + ldc8) * 2, src, (grow[i] >= 0) ? 16 : 0);
            }
#pragma unroll
            for (int i = 0; i < 4; i++) {
                int row = ldrow + i * 32;
                cp16(smB[pf] + (row * SKS + ldc8) * 2, B + (size_t)(n0 + row) * K + k0 + ldc8, 16);
            }
        }
        cp_commit();

        const uint32_t sA = smA[cur], sB = smB[cur];
#pragma unroll
        for (int ks = 0; ks < 4; ks++) {
            const uint32_t kk2 = ks * 32;
            uint32_t af[4][4], bf[4][2];
#pragma unroll
            for (int mt = 0; mt < 4; mt++)
                ldm_x4(af[mt], sA + aoff + mt * 16 * SKS * 2 + kk2);
#pragma unroll
            for (int ntp = 0; ntp < 2; ntp++) {
                uint32_t tmp[4];
                ldm_x4(tmp, sB + boff + ntp * 16 * SKS * 2 + kk2);
                bf[2 * ntp][0] = tmp[0]; bf[2 * ntp][1] = tmp[1];
                bf[2 * ntp + 1][0] = tmp[2]; bf[2 * ntp + 1][1] = tmp[3];
            }
#pragma unroll
            for (int mt = 0; mt < 4; mt++)
#pragma unroll
                for (int nt = 0; nt < 4; nt++)
                    mma_h(acc[mt][nt], af[mt], bf[nt]);
        }
        cur = (cur + 1 == NSTG) ? 0 : cur + 1;
        pf = (pf + 1 == NSTG) ? 0 : pf + 1;
    }

#pragma unroll
    for (int mt = 0; mt < 4; mt++) {
        int r = warp_m + mt * 16 + g;
#pragma unroll
        for (int nt = 0; nt < 4; nt++) {
            int gc = n0 + warp_n + nt * 8 + tig * 2;
            if (m0 + r < cnt)
                *(__half2*)(Ch + (size_t)(start + m0 + r) * N + gc) =
                    __floats2half2_rn(acc[mt][nt][0], acc[mt][nt][1]);
            if (m0 + r + 8 < cnt)
                *(__half2*)(Ch + (size_t)(start + m0 + r + 8) * N + gc) =
                    __floats2half2_rn(acc[mt][nt][2], acc[mt][nt][3]);
        }
    }
}

// ---------------- fp16 flash attention ----------------
__global__ __launch_bounds__(256) void attn_h_kernel() {
    extern __shared__ __half smh[];
    __half* Qs  = smh;
    __half* Ksb = Qs + AQ * QST;
    __half* Vsb = Ksb + 2 * AK * KST;
    __half* Ps  = Vsb + 2 * AK * VST;

    const int h = blockIdx.y;
    const int qb = gridDim.x - 1 - blockIdx.x;
    const int q0 = qb * AQ;
    const int tid = threadIdx.x;
    const int warp = tid >> 5, lane = tid & 31;
    const int g = lane >> 2, tig = lane & 3;
    const int row0 = warp * 16 + g;
    const int qi0 = q0 + row0, qi1 = qi0 + 8;

    uint32_t smK[2], smV[2];
    smK[0] = (uint32_t)__cvta_generic_to_shared(Ksb);
    smK[1] = (uint32_t)__cvta_generic_to_shared(Ksb + AK * KST);
    smV[0] = (uint32_t)__cvta_generic_to_shared(Vsb);
    smV[1] = (uint32_t)__cvta_generic_to_shared(Vsb + AK * VST);
    const uint32_t smQ = (uint32_t)__cvta_generic_to_shared(Qs);
    const uint32_t smP = (uint32_t)__cvta_generic_to_shared(Ps);

    const uint32_t qoff = smQ + ((warp * 16 + (lane & 15)) * QST + ((lane >> 4) << 3)) * 2;
    const uint32_t koff = ((((lane >> 4) & 1) * 8 + (lane & 7)) * KST
                            + (((lane >> 3) & 1) << 3)) * 2;
    const uint32_t poff = smP + ((warp * 16 + (lane & 15)) * PST + ((lane >> 4) << 3)) * 2;
    const uint32_t voff = ((lane & 15) * VST + ((lane >> 4) & 1) * 8) * 2;

#pragma unroll
    for (int i = 0; i < 12; i++) {
        int idx = tid + i * 256;
        int r = idx / 24, c = (idx % 24) * 8;
        *(float4*)(Qs + r * QST + c) =
            *(const float4*)(a_q + ((size_t)(q0 + r) * NHEAD + h) * DQK + c);
    }

    float acc[16][4];
#pragma unroll
    for (int n = 0; n < 16; n++)
#pragma unroll
        for (int c = 0; c < 4; c++) acc[n][c] = 0.f;
    float m0 = -1e30f, m1 = -1e30f, l0 = 0.f, l1 = 0.f;
    const float scale = 0.07216878364870323f;

    const int ntiles = qb * 2 + 2;

    {
#pragma unroll
        for (int i = 0; i < 6; i++) {
            int idx = tid + i * 256;
            int r = idx / 24, c = (idx % 24) * 8;
            cp16(smK[0] + (r * KST + c) * 2,
                 a_kv + ((size_t)r * NHEAD + h) * (DQK + DV) + c, 16);
        }
#pragma unroll
        for (int i = 0; i < 4; i++) {
            int idx = tid + i * 256;
            int r = idx >> 4, c = (idx & 15) * 8;
            cp16(smV[0] + (r * VST + c) * 2,
                 a_kv + ((size_t)r * NHEAD + h) * (DQK + DV) + DQK + c, 16);
        }
        cp_commit();
    }

    for (int tile = 0; tile < ntiles; tile++) {
        const int cur = tile & 1, nb = cur ^ 1;
        __syncthreads();
        if (tile + 1 < ntiles) {
            int t1 = (tile + 1) * AK;
#pragma unroll
            for (int i = 0; i < 6; i++) {
                int idx = tid + i * 256;
                int r = idx / 24, c = (idx % 24) * 8;
                cp16(smK[nb] + (r * KST + c) * 2,
                     a_kv + ((size_t)(t1 + r) * NHEAD + h) * (DQK + DV) + c, 16);
            }
#pragma unroll
            for (int i = 0; i < 4; i++) {
                int idx = tid + i * 256;
                int r = idx >> 4, c = (idx & 15) * 8;
                cp16(smV[nb] + (r * VST + c) * 2,
                     a_kv + ((size_t)(t1 + r) * NHEAD + h) * (DQK + DV) + DQK + c, 16);
            }
            cp_commit();
            cp_wait1();
        } else {
            cp_wait0();
        }
        __syncthreads();

        const int t0 = tile * AK;
        float s[8][4];
#pragma unroll
        for (int n = 0; n < 8; n++)
#pragma unroll
            for (int c = 0; c < 4; c++) s[n][c] = 0.f;
#pragma unroll
        for (int ks = 0; ks < 12; ks++) {
            const uint32_t kk2 = ks * 32;
            uint32_t af[4];
            ldm_x4(af, qoff + kk2);
#pragma unroll
            for (int ntp = 0; ntp < 4; ntp++) {
                uint32_t tmp[4];
                ldm_x4(tmp, smK[cur] + koff + ntp * 16 * KST * 2 + kk2);
                mma_h(s[2 * ntp],     af, tmp);
                mma_h(s[2 * ntp + 1], af, tmp + 2);
            }
        }

        const bool domask = (t0 + AK - 1 > q0);
#pragma unroll
        for (int nt = 0; nt < 8; nt++) {
#pragma unroll
            for (int c = 0; c < 4; c++) s[nt][c] *= scale;
            if (domask) {
                int kj = t0 + nt * 8 + tig * 2;
                if (kj > qi0)     s[nt][0] = -1e30f;
                if (kj + 1 > qi0) s[nt][1] = -1e30f;
                if (kj > qi1)     s[nt][2] = -1e30f;
                if (kj + 1 > qi1) s[nt][3] = -1e30f;
            }
        }

        float mx0 = -1e30f, mx1 = -1e30f;
#pragma unroll
        for (int nt = 0; nt < 8; nt++) {
            mx0 = fmaxf(mx0, fmaxf(s[nt][0], s[nt][1]));
            mx1 = fmaxf(mx1, fmaxf(s[nt][2], s[nt][3]));
        }
        mx0 = fmaxf(mx0, __shfl_xor_sync(0xffffffffu, mx0, 1));
        mx0 = fmaxf(mx0, __shfl_xor_sync(0xffffffffu, mx0, 2));
        mx1 = fmaxf(mx1, __shfl_xor_sync(0xffffffffu, mx1, 1));
        mx1 = fmaxf(mx1, __shfl_xor_sync(0xffffffffu, mx1, 2));

        float mn0 = fmaxf(m0, mx0), mn1 = fmaxf(m1, mx1);
        float cf0 = __expf(m0 - mn0), cf1 = __expf(m1 - mn1);
        m0 = mn0; m1 = mn1;

        float sum0 = 0.f, sum1 = 0.f;
#pragma unroll
        for (int nt = 0; nt < 8; nt++) {
            float p0 = __expf(s[nt][0] - m0);
            float p1 = __expf(s[nt][1] - m0);
            float p2 = __expf(s[nt][2] - m1);
            float p3 = __expf(s[nt][3] - m1);
            sum0 += p0 + p1; sum1 += p2 + p3;
            *(__half2*)(Ps + row0 * PST + nt * 8 + tig * 2) = __floats2half2_rn(p0, p1);
            *(__half2*)(Ps + (row0 + 8) * PST + nt * 8 + tig * 2) = __floats2half2_rn(p2, p3);
        }
        sum0 += __shfl_xor_sync(0xffffffffu, sum0, 1);
        sum0 += __shfl_xor_sync(0xffffffffu, sum0, 2);
        sum1 += __shfl_xor_sync(0xffffffffu, sum1, 1);
        sum1 += __shfl_xor_sync(0xffffffffu, sum1, 2);
        l0 = l0 * cf0 + sum0;
        l1 = l1 * cf1 + sum1;
#pragma unroll
        for (int nt = 0; nt < 16; nt++) {
            acc[nt][0] *= cf0; acc[nt][1] *= cf0;
            acc[nt][2] *= cf1; acc[nt][3] *= cf1;
        }
        __syncwarp();

#pragma unroll
        for (int ks = 0; ks < 4; ks++) {
            uint32_t af[4];
            ldm_x4(af, poff + ks * 32);
            const uint32_t vbase = smV[cur] + voff + (uint32_t)(ks * 16) * VST * 2;
#pragma unroll
            for (int ntp = 0; ntp < 8; ntp++) {
                uint32_t tmp[4];
                ldm_x4_t(tmp, vbase + ntp * 16 * 2);
                mma_h(acc[2 * ntp],     af, tmp);
                mma_h(acc[2 * ntp + 1], af, tmp + 2);
            }
        }
    }

    float inv0 = 1.0f / l0, inv1 = 1.0f / l1;
#pragma unroll
    for (int nt = 0; nt < 16; nt++) {
        int col = h * DV + nt * 8 + tig * 2;
        *(__half2*)(a_ctx + (size_t)qi0 * (NHEAD * DV) + col) =
            __floats2half2_rn(acc[nt][0] * inv0, acc[nt][1] * inv0);
        *(__half2*)(a_ctx + (size_t)qi1 * (NHEAD * DV) + col) =
            __floats2half2_rn(acc[nt][2] * inv1, acc[nt][3] * inv1);
    }
}

// ---------------- RMSNorm: one-pass, float4, register-cached ----------------
__global__ void rmsnorm_h(const float* in, const float* w, __half* out, float* outf, int D) {
    int t = blockIdx.x;
    const float4* row = (const float4*)(in + (size_t)t * D);
    const int n4 = D >> 2;
    float4 cache[2];
    int cnt = 0;
    float ss = 0.f;
    for (int i = threadIdx.x; i < n4; i += 256) {
        float4 v = row[i];
        cache[cnt++] = v;
        ss += v.x * v.x + v.y * v.y + v.z * v.z + v.w * v.w;
    }
    __shared__ float sred[32];
    for (int o = 16; o > 0; o >>= 1) ss += __shfl_down_sync(0xffffffffu, ss, o);
    int lane = threadIdx.x & 31, warp = threadIdx.x >> 5;
    if (lane == 0) sred[warp] = ss;
    __syncthreads();
    if (threadIdx.x == 0) {
        float tot = 0.f;
        for (int i = 0; i < 8; i++) tot += sred[i];
        sred[0] = 1.0f / sqrtf(tot / (float)D + 1e-6f);
    }
    __syncthreads();
    float scale = sred[0];
    cnt = 0;
    for (int i = threadIdx.x; i < n4; i += 256) {
        float4 v = cache[cnt++];
        const float4 wv = *(const float4*)(w + 4 * i);
        float r0 = v.x * scale * wv.x, r1 = v.y * scale * wv.y;
        float r2 = v.z * scale * wv.z, r3 = v.w * scale * wv.w;
        __half2 p[2];
        p[0] = __floats2half2_rn(r0, r1);
        p[1] = __floats2half2_rn(r2, r3);
        *(float2*)(out + (size_t)t * D + 4 * i) = *(float2*)p;
        if (outf) *(float4*)(outf + (size_t)t * D + 4 * i) = make_float4(r0, r1, r2, r3);
    }
}

// ---------------- RoPE ----------------
__global__ void rope_h_kernel() {
    int idx = blockIdx.x * blockDim.x + threadIdx.x;
    int total = SEQ * NHEAD * (ROPED / 2);
    if (idx >= total) return;
    int i = idx & 31;
    int h = (idx >> 5) & (NHEAD - 1);
    int t = idx >> 9;
    float inv_freq = powf(10000.0f, -(float)(2 * i) / (float)ROPED);
    float f = (float)t * inv_freq;
    float c = cosf(f), s = sinf(f);
    __half* qp = a_q + ((size_t)t * NHEAD + h) * DQK + NOPE;
    float x1 = __half2float(qp[i]), x2 = __half2float(qp[i + 32]);
    qp[i] = __float2half(x1 * c - x2 * s);
    qp[i + 32] = __float2half(x2 * c + x1 * s);
    __half* kp = a_kv + ((size_t)t * NHEAD + h) * (DQK + DV) + NOPE;
    x1 = __half2float(kp[i]); x2 = __half2float(kp[i + 32]);
    kp[i] = __float2half(x1 * c - x2 * s);
    kp[i + 32] = __float2half(x2 * c + x1 * s);
}

// ---------------- Router (fp32 h2) — also zeroes expert counters ----------------
__global__ void router_kernel(const float* __restrict__ rw, const float* __restrict__ rb) {
    int t = blockIdx.x;
    if (t == 0 && threadIdx.x < NEXP) { g_cnt[threadIdx.x] = 0; g_fill[threadIdx.x] = 0; }
    float part[NEXP];
#pragma unroll
    for (int e = 0; e < NEXP; e++) part[e] = 0.f;
    for (int hh = threadIdx.x; hh < HDIM; hh += 128) {
        float xv = g_h2f[(size_t)t * HDIM + hh];
#pragma unroll
        for (int e = 0; e < NEXP; e++) part[e] += xv * rw[(size_t)e * HDIM + hh];
    }
    __shared__ float sred[4][NEXP];
#pragma unroll
    for (int e = 0; e < NEXP; e++)
        for (int o = 16; o > 0; o >>= 1) part[e] += __shfl_down_sync(0xffffffffu, part[e], o);
    int lane = threadIdx.x & 31, warp = threadIdx.x >> 5;
    if (lane == 0)
#pragma unroll
        for (int e = 0; e < NEXP; e++) sred[warp][e] = part[e];
    __syncthreads();
    if (threadIdx.x < NEXP) {
        int e = threadIdx.x;
        g_logits[t * NEXP + e] = sred[0][e] + sred[1][e] + sred[2][e] + sred[3][e] + rb[e];
    }
}

__global__ void topk_kernel() {
    int t = blockIdx.x * blockDim.x + threadIdx.x;
    if (t >= SEQ) return;
    float p[NEXP];
#pragma unroll
    for (int e = 0; e < NEXP; e++) p[e] = 1.0f / (1.0f + expf(-g_logits[t * NEXP + e]));
    float vals[TOPK]; int ids[TOPK];
    float sum = 0.f;
#pragma unroll
    for (int k = 0; k < TOPK; k++) {
        float best = -1e30f; int bi = 0;
#pragma unroll
        for (int e = 0; e < NEXP; e++)
            if (p[e] > best) { best = p[e]; bi = e; }
        vals[k] = best; ids[k] = bi; p[bi] = -1e30f; sum += best;
    }
    float w = 2.5f / (sum + 1e-9f);
#pragma unroll
    for (int k = 0; k < TOPK; k++) {
        g_wtop[t * TOPK + k] = vals[k] * w;
        g_topi[t * TOPK + k] = ids[k];
        atomicAdd(&g_cnt[ids[k]], 1);
    }
}

__global__ void offsets_kernel() {
    if (threadIdx.x == 0) {
        g_off[0] = 0;
        for (int e = 0; e < NEXP; e++) g_off[e + 1] = g_off[e] + g_cnt[e];
    }
}

__global__ void scatter_kernel() {
    int t = blockIdx.x * blockDim.x + threadIdx.x;
    if (t >= SEQ) return;
#pragma unroll
    for (int k = 0; k < TOPK; k++) {
        int e = g_topi[t * TOPK + k];
        int pos = atomicAdd(&g_fill[e], 1);
        int slot = g_off[e] + pos;
        g_slot[t * TOPK + k] = slot;
        g_tok[slot] = t;
    }
}

// ---------------- SiLU(a)*b, fp16 ----------------
__global__ void act_h_kernel(__half2* a, const __half2* b, size_t n2) {
    size_t i = (size_t)blockIdx.x * blockDim.x + threadIdx.x;
    if (i >= n2) return;
    float2 gg = __half22float2(a[i]);
    float2 uu = __half22float2(b[i]);
    gg.x = gg.x / (1.0f + expf(-gg.x)) * uu.x;
    gg.y = gg.y / (1.0f + expf(-gg.y)) * uu.y;
    a[i] = __floats2half2_rn(gg.x, gg.y);
}

// ---------------- Final combine (float4) ----------------
__global__ void combine_kernel(float* out) {
    int t = blockIdx.x;
    float w[TOPK]; int s[TOPK];
#pragma unroll
    for (int k = 0; k < TOPK; k++) { w[k] = g_wtop[t * TOPK + k]; s[k] = g_slot[t * TOPK + k]; }
    for (int i = threadIdx.x; i < HDIM / 4; i += 256) {
        float4 v = *(const float4*)(g_xmid + (size_t)t * HDIM + 4 * i);
        float4 sh = *(const float4*)(g_shr + (size_t)t * HDIM + 4 * i);
        v.x += sh.x; v.y += sh.y; v.z += sh.z; v.w += sh.w;
#pragma unroll
        for (int k = 0; k < TOPK; k++) {
            float2 d01 = __half22float2(*(const __half2*)(a_down + (size_t)s[k] * HDIM + 4 * i));
            float2 d23 = __half22float2(*(const __half2*)(a_down + (size_t)s[k] * HDIM + 4 * i + 2));
            v.x += w[k] * d01.x; v.y += w[k] * d01.y;
            v.z += w[k] * d23.x; v.w += w[k] * d23.y;
        }
        *(float4*)(out + (size_t)t * HDIM + 4 * i) = v;
    }
}

// ---------------- host ----------------
static float* symf(const void* sym) { void* p = nullptr; cudaGetSymbolAddress(&p, sym); return (float*)p; }
static __half* symh(const void* sym) { void* p = nullptr; cudaGetSymbolAddress(&p, sym); return (__half*)p; }
static int*   symi(const void* sym) { void* p = nullptr; cudaGetSymbolAddress(&p, sym); return (int*)p; }

extern "C" void kernel_launch(void* const* d_in, const int* in_sizes, int n_in,
                              void* d_out, int out_size)
{
    const float* x      = (const float*)d_in[0];
    const float* ln1_w  = (const float*)d_in[2];
    const float* ln2_w  = (const float*)d_in[3];
    const float* q_a_w  = (const float*)d_in[4];
    const float* q_a_ln = (const float*)d_in[5];
    const float* q_b_w  = (const float*)d_in[6];
    const float* kv_a_w = (const float*)d_in[7];
    const float* kv_a_ln= (const float*)d_in[8];
    const float* kv_b_w = (const float*)d_in[9];
    const float* o_w    = (const float*)d_in[10];
    const float* rout_w = (const float*)d_in[11];
    const float* rout_b = (const float*)d_in[12];
    const float* gate_w = (const float*)d_in[13];
    const float* up_w   = (const float*)d_in[14];
    const float* down_w = (const float*)d_in[15];
    const float* sg_w   = (const float*)d_in[16];
    const float* su_w   = (const float*)d_in[17];
    const float* sd_w   = (const float*)d_in[18];
    float* out = (float*)d_out;

    __half* wqa  = symh(w_qa);   __half* wkva = symh(w_kva);
    __half* wqb  = symh(w_qb);   __half* wkvb = symh(w_kvb);
    __half* wo   = symh(w_o);
    __half* wg   = symh(w_gate); __half* wu   = symh(w_up);  __half* wd = symh(w_down);
    __half* wsg  = symh(w_sg);   __half* wsu  = symh(w_su);  __half* wsd = symh(w_sd);

    __half* h1h  = symh(a_h1);
    __half* qah  = symh(a_qa);   __half* kvah = symh(a_kva);
    __half* qh   = symh(a_q);    __half* kvh  = symh(a_kv);
    __half* ctxh = symh(a_ctx);  __half* h2h  = symh(a_h2);
    __half* gth  = symh(a_gate); __half* uph  = symh(a_up);
    __half* dnh  = symh(a_down);
    __half* sgh  = symh(a_sg);   __half* suh  = symh(a_su);

    float* qaf  = symf(g_qa);   float* kvaf = symf(g_kva);
    float* xmid = symf(g_xmid); float* h2f  = symf(g_h2f);
    float* shr  = symf(g_shr);
    int* tok = symi(g_tok);     int* off = symi(g_off);

    cudaFuncSetAttribute(gemm_h, cudaFuncAttributeMaxDynamicSharedMemorySize, GSMEM);
    cudaFuncSetAttribute(gemm_h_moe, cudaFuncAttributeMaxDynamicSharedMemorySize, GSMEM);
    cudaFuncSetAttribute(attn_h_kernel, cudaFuncAttributeMaxDynamicSharedMemorySize, ATTN_SMEM);

    // ---- batched weight conversion (one launch, default stream) ----
    {
        ConvBatch cb;
        const float* ins[NSEG] = { q_a_w, kv_a_w, q_b_w, kv_b_w, o_w,
                                   gate_w, up_w, down_w, sg_w, su_w, sd_w };
        __half* outs[NSEG] = { wqa, wkva, wqb, wkvb, wo, wg, wu, wd, wsg, wsu, wsd };
        size_t ns[NSEG] = {
            (size_t)QRNK * HDIM, (size_t)KVRNK * HDIM,
            (size_t)NHEAD * DQK * QRNK, (size_t)NHEAD * (DQK + DV) * KVRNK,
            (size_t)HDIM * NHEAD * DV,
            (size_t)NEXP * MINT * HDIM, (size_t)NEXP * MINT * HDIM,
            (size_t)NEXP * HDIM * MINT,
            (size_t)MINT * HDIM, (size_t)MINT * HDIM, (size_t)HDIM * MINT };
        int acc = 0;
        for (int s = 0; s < NSEG; s++) {
            cb.in[s] = (const float4*)ins[s];
            cb.out[s] = outs[s];
            cb.start[s] = acc;
            acc += (int)(ns[s] / 4);
        }
        cb.start[NSEG] = acc;
        conv_batch_kernel<<<(acc + 255) / 256, 256>>>(cb);
    }

    // ---- attention branch ----
    rmsnorm_h<<<SEQ, 256>>>(x, ln1_w, h1h, nullptr, HDIM);
    gemm_h<<<dim3((QRNK + KVRNK) / BN, SEQ / BM), 256, GSMEM>>>(
        h1h, wqa, qaf, nullptr, nullptr, QRNK, HDIM,
        h1h, wkva, kvaf, nullptr, KVRNK, HDIM, SEQ);
    rmsnorm_h<<<SEQ, 256>>>(qaf, q_a_ln, qah, nullptr, QRNK);
    rmsnorm_h<<<SEQ, 256>>>(kvaf, kv_a_ln, kvah, nullptr, KVRNK);
    gemm_h<<<dim3((NHEAD * DQK + NHEAD * (DQK + DV)) / BN, SEQ / BM), 256, GSMEM>>>(
        qah, wqb, nullptr, qh, nullptr, NHEAD * DQK, QRNK,
        kvah, wkvb, nullptr, kvh, NHEAD * (DQK + DV), KVRNK, SEQ);
    rope_h_kernel<<<(SEQ * NHEAD * (ROPED / 2) + 255) / 256, 256>>>();
    attn_h_kernel<<<dim3(SEQ / AQ, NHEAD), 256, ATTN_SMEM>>>();
    gemm_h<<<dim3(HDIM / BN, SEQ / BM), 256, GSMEM>>>(
        ctxh, wo, xmid, nullptr, x, HDIM, NHEAD * DV,
        nullptr, nullptr, nullptr, nullptr, 0, BK, SEQ);

    // ---- MoE branch ----
    rmsnorm_h<<<SEQ, 256>>>(xmid, ln2_w, h2h, h2f, HDIM);
    router_kernel<<<SEQ, 128>>>(rout_w, rout_b);
    topk_kernel<<<SEQ / 256, 256>>>();
    offsets_kernel<<<1, 1>>>();
    scatter_kernel<<<SEQ / 256, 256>>>();

    gemm_h_moe<<<dim3(2 * MINT / BN, SEQ / BM, NEXP), 256, GSMEM>>>(
        h2h, tok, wg, gth, MINT, wu, uph, MINT, (size_t)MINT * HDIM, HDIM, off);
    act_h_kernel<<<(unsigned)(((size_t)NSLOT * MINT / 2 + 255) / 256), 256>>>(
        (__half2*)gth, (const __half2*)uph, (size_t)NSLOT * MINT / 2);
    gemm_h_moe<<<dim3(HDIM / BN, SEQ / BM, NEXP), 256, GSMEM>>>(
        gth, nullptr, wd, dnh, HDIM, nullptr, nullptr, 0, (size_t)HDIM * MINT, MINT, off);

    // shared expert
    gemm_h<<<dim3(2 * MINT / BN, SEQ / BM), 256, GSMEM>>>(
        h2h, wsg, nullptr, sgh, nullptr, MINT, HDIM,
        h2h, wsu, nullptr, suh, MINT, HDIM, SEQ);
    act_h_kernel<<<(unsigned)(((size_t)SEQ * MINT / 2 + 255) / 256), 256>>>(
        (__half2*)sgh, (const __half2*)suh, (size_t)SEQ * MINT / 2);
    gemm_h<<<dim3(HDIM / BN, SEQ / BM), 256, GSMEM>>>(
        sgh, wsd, shr, nullptr, nullptr, HDIM, MINT,
        nullptr, nullptr, nullptr, nullptr, 0, BK, SEQ);

    combine_kernel<<<SEQ, 256>>>(out);
}

// round 14
// speedup vs baseline: 1.3573x; 1.0086x over previous
#include <cuda_runtime.h>
#include <cuda_fp16.h>
#include <math.h>
#include <stdint.h>

// ---------------- problem constants ----------------
#define SEQ   2048
#define HDIM  2048
#define NHEAD 16
#define DQK   192
#define DV    128
#define NOPE  128
#define ROPED 64
#define QRNK  768
#define KVRNK 512
#define NEXP  16
#define TOPK  4
#define MINT  1024
#define NSLOT (SEQ*TOPK)

// GEMM tiling (fp16, m16n8k16), 3-stage pipeline
#define BM 128
#define BN 128
#define BK 64
#define SKS 72
#define NSTG 3
#define GSMEM (NSTG*(BM+BN)*SKS*2)
#define BNF 64      // fused gate/up kernel N tile

// attention tiling (double-buffered K/V)
#define AQ 128
#define AK 64
#define QST 200
#define KST 200
#define VST 136
#define PST 72
#define ATTN_SMEM ((AQ*QST + 2*AK*KST + 2*AK*VST + AQ*PST)*2)

// ---------------- fp32 scratch ----------------
__device__ float g_qa[SEQ*QRNK];
__device__ float g_kva[SEQ*KVRNK];
__device__ float g_xmid[SEQ*HDIM];
__device__ float g_h2f[SEQ*HDIM];
__device__ float g_shr[SEQ*HDIM];
__device__ float g_logits[SEQ*NEXP];
__device__ float g_wtop[SEQ*TOPK];
__device__ int   g_topi[SEQ*TOPK];
__device__ int   g_slot[SEQ*TOPK];
__device__ int   g_cnt[NEXP];
__device__ int   g_off[NEXP+1];
__device__ int   g_fill[NEXP];
__device__ int   g_tok[NSLOT];
__device__ int   g_off_shared[2] = {0, SEQ};

// ---------------- fp16 weights ----------------
__device__ __half w_qa[QRNK*HDIM];
__device__ __half w_kva[KVRNK*HDIM];
__device__ __half w_qb[NHEAD*DQK*QRNK];
__device__ __half w_kvb[NHEAD*(DQK+DV)*KVRNK];
__device__ __half w_o[HDIM*NHEAD*DV];
__device__ __half w_gate[(size_t)NEXP*MINT*HDIM];
__device__ __half w_up[(size_t)NEXP*MINT*HDIM];
__device__ __half w_down[(size_t)NEXP*HDIM*MINT];
__device__ __half w_sg[MINT*HDIM];
__device__ __half w_su[MINT*HDIM];
__device__ __half w_sd[HDIM*MINT];

// ---------------- fp16 activations ----------------
__device__ __half a_h1[SEQ*HDIM];
__device__ __half a_qa[SEQ*QRNK];
__device__ __half a_kva[SEQ*KVRNK];
__device__ __half a_q[SEQ*NHEAD*DQK];
__device__ __half a_kv[SEQ*NHEAD*(DQK+DV)];
__device__ __half a_ctx[SEQ*NHEAD*DV];
__device__ __half a_h2[SEQ*HDIM];
__device__ __half a_gate[(size_t)NSLOT*MINT];
__device__ __half a_down[(size_t)NSLOT*HDIM];
__device__ __half a_sg[SEQ*MINT];

// ---------------- helpers ----------------
__device__ __forceinline__ void cp16(uint32_t dst, const void* src, int szbytes) {
    asm volatile("cp.async.cg.shared.global [%0], [%1], 16, %2;\n"
                 :: "r"(dst), "l"(src), "r"(szbytes));
}
__device__ __forceinline__ void cp_commit() { asm volatile("cp.async.commit_group;\n"); }
__device__ __forceinline__ void cp_wait0()  { asm volatile("cp.async.wait_group 0;\n"); }
__device__ __forceinline__ void cp_wait1()  { asm volatile("cp.async.wait_group 1;\n"); }

__device__ __forceinline__ void mma_h(float* c, const uint32_t* a, const uint32_t* b) {
    asm volatile(
        "mma.sync.aligned.m16n8k16.row.col.f32.f16.f16.f32 "
        "{%0,%1,%2,%3}, {%4,%5,%6,%7}, {%8,%9}, {%0,%1,%2,%3};\n"
        : "+f"(c[0]), "+f"(c[1]), "+f"(c[2]), "+f"(c[3])
        : "r"(a[0]), "r"(a[1]), "r"(a[2]), "r"(a[3]), "r"(b[0]), "r"(b[1]));
}
__device__ __forceinline__ void ldm_x4(uint32_t* r, uint32_t addr) {
    asm volatile("ldmatrix.sync.aligned.m8n8.x4.shared.b16 {%0,%1,%2,%3}, [%4];"
                 : "=r"(r[0]), "=r"(r[1]), "=r"(r[2]), "=r"(r[3]) : "r"(addr));
}
__device__ __forceinline__ void ldm_x4_t(uint32_t* r, uint32_t addr) {
    asm volatile("ldmatrix.sync.aligned.m8n8.x4.trans.shared.b16 {%0,%1,%2,%3}, [%4];"
                 : "=r"(r[0]), "=r"(r[1]), "=r"(r[2]), "=r"(r[3]) : "r"(addr));
}
__device__ __forceinline__ float silu_mul(float gv, float uv) {
    return gv / (1.0f + expf(-gv)) * uv;
}

// ---------------- batched fp32 -> fp16 convert ----------------
#define NSEG 11
struct ConvBatch {
    const float4* in[NSEG];
    __half* out[NSEG];
    int start[NSEG + 1];
};
__global__ void conv_batch_kernel(ConvBatch cb) {
    int i = blockIdx.x * blockDim.x + threadIdx.x;
    if (i >= cb.start[NSEG]) return;
    int seg = 0;
#pragma unroll
    for (int s = 1; s < NSEG; s++) seg += (i >= cb.start[s]);
    int local = i - cb.start[seg];
    float4 v = __ldcs(cb.in[seg] + local);
    __half2 p[2];
    p[0] = __floats2half2_rn(v.x, v.y);
    p[1] = __floats2half2_rn(v.z, v.w);
    __stcs((float2*)(cb.out[seg] + (size_t)local * 4), *(float2*)p);
}

// ---------------- fp16 tensor-core GEMM (dual segment, 3-stage) ----------------
__global__ __launch_bounds__(256, 2) void gemm_h(
    const __half* __restrict__ A1,
    const __half* __restrict__ B1, float* C1, __half* C1h, const float* add1, int N1, int K1,
    const __half* __restrict__ A2,
    const __half* __restrict__ B2, float* C2, __half* C2h, int N2, int K2,
    int M)
{
    extern __shared__ __half smh[];

    int n0 = blockIdx.x * BN;
    const __half *A, *B; float* C; __half* Ch; const float* addsrc; int N, K;
    if (n0 < N1) { A = A1; B = B1; C = C1; Ch = C1h; addsrc = add1; N = N1; K = K1; }
    else { n0 -= N1; A = A2; B = B2; C = C2; Ch = C2h; addsrc = nullptr; N = N2; K = K2; }

    const int tid = threadIdx.x;
    const int warp = tid >> 5, lane = tid & 31;
    const int g = lane >> 2, tig = lane & 3;
    const int warp_m = (warp & 1) * 64, warp_n = (warp >> 1) * 32;
    const int m0 = blockIdx.y * BM;

    float acc[4][4][4];
#pragma unroll
    for (int a = 0; a < 4; a++)
#pragma unroll
        for (int b = 0; b < 4; b++)
#pragma unroll
            for (int c = 0; c < 4; c++) acc[a][b][c] = 0.f;

    const int nk = K / BK;
    uint32_t smA[NSTG], smB[NSTG];
#pragma unroll
    for (int s = 0; s < NSTG; s++) {
        smA[s] = (uint32_t)__cvta_generic_to_shared(smh + s * BM * SKS);
        smB[s] = (uint32_t)__cvta_generic_to_shared(smh + NSTG * BM * SKS + s * BN * SKS);
    }

    const int ldrow = tid >> 3, ldc8 = (tid & 7) << 3;
    const uint32_t aoff = ((warp_m + (lane & 15)) * SKS + ((lane >> 4) << 3)) * 2;
    const uint32_t boff = ((warp_n + ((lane >> 4) & 1) * 8 + (lane & 7)) * SKS
                           + (((lane >> 3) & 1) << 3)) * 2;

#pragma unroll
    for (int s = 0; s < 2; s++) {
        int k0 = s * BK;
#pragma unroll
        for (int i = 0; i < 4; i++) {
            int row = ldrow + i * 32;
            cp16(smA[s] + (row * SKS + ldc8) * 2, A + (size_t)(m0 + row) * K + k0 + ldc8, 16);
        }
#pragma unroll
        for (int i = 0; i < 4; i++) {
            int row = ldrow + i * 32;
            cp16(smB[s] + (row * SKS + ldc8) * 2, B + (size_t)(n0 + row) * K + k0 + ldc8, 16);
        }
        cp_commit();
    }

    int cur = 0, pf = 2;
    for (int kt = 0; kt < nk; kt++) {
        cp_wait1();
        __syncthreads();
        if (kt + 2 < nk) {
            int k0 = (kt + 2) * BK;
#pragma unroll
            for (int i = 0; i < 4; i++) {
                int row = ldrow + i * 32;
                cp16(smA[pf] + (row * SKS + ldc8) * 2, A + (size_t)(m0 + row) * K + k0 + ldc8, 16);
            }
#pragma unroll
            for (int i = 0; i < 4; i++) {
                int row = ldrow + i * 32;
                cp16(smB[pf] + (row * SKS + ldc8) * 2, B + (size_t)(n0 + row) * K + k0 + ldc8, 16);
            }
        }
        cp_commit();

        const uint32_t sA = smA[cur], sB = smB[cur];
#pragma unroll
        for (int ks = 0; ks < 4; ks++) {
            const uint32_t kk2 = ks * 32;
            uint32_t af[4][4], bf[4][2];
#pragma unroll
            for (int mt = 0; mt < 4; mt++)
                ldm_x4(af[mt], sA + aoff + mt * 16 * SKS * 2 + kk2);
#pragma unroll
            for (int ntp = 0; ntp < 2; ntp++) {
                uint32_t tmp[4];
                ldm_x4(tmp, sB + boff + ntp * 16 * SKS * 2 + kk2);
                bf[2 * ntp][0] = tmp[0]; bf[2 * ntp][1] = tmp[1];
                bf[2 * ntp + 1][0] = tmp[2]; bf[2 * ntp + 1][1] = tmp[3];
            }
#pragma unroll
            for (int mt = 0; mt < 4; mt++)
#pragma unroll
                for (int nt = 0; nt < 4; nt++)
                    mma_h(acc[mt][nt], af[mt], bf[nt]);
        }
        cur = (cur + 1 == NSTG) ? 0 : cur + 1;
        pf = (pf + 1 == NSTG) ? 0 : pf + 1;
    }

#pragma unroll
    for (int mt = 0; mt < 4; mt++) {
        int r0 = m0 + warp_m + mt * 16 + g;
#pragma unroll
        for (int nt = 0; nt < 4; nt++) {
            int gc = n0 + warp_n + nt * 8 + tig * 2;
            float v0 = acc[mt][nt][0], v1 = acc[mt][nt][1];
            float v2 = acc[mt][nt][2], v3 = acc[mt][nt][3];
            if (addsrc) {
                v0 += addsrc[(size_t)r0 * N + gc];
                v1 += addsrc[(size_t)r0 * N + gc + 1];
                v2 += addsrc[(size_t)(r0 + 8) * N + gc];
                v3 += addsrc[(size_t)(r0 + 8) * N + gc + 1];
            }
            if (C) {
                *(float2*)(C + (size_t)r0 * N + gc) = make_float2(v0, v1);
                *(float2*)(C + (size_t)(r0 + 8) * N + gc) = make_float2(v2, v3);
            }
            if (Ch) {
                *(__half2*)(Ch + (size_t)r0 * N + gc) = __floats2half2_rn(v0, v1);
                *(__half2*)(Ch + (size_t)(r0 + 8) * N + gc) = __floats2half2_rn(v2, v3);
            }
        }
    }
}

// ---------------- fp16 grouped MoE GEMM (single-B, gathered A, 3-stage) ----------------
__global__ __launch_bounds__(256, 2) void gemm_h_moe(
    const __half* __restrict__ A, const int* __restrict__ gather,
    const __half* __restrict__ B1b, __half* C1h, int N1,
    size_t strideB, int K, const int* __restrict__ off)
{
    const int e = blockIdx.z;
    const int start = off[e];
    const int cnt = off[e + 1] - start;
    const int m0 = blockIdx.y * BM;
    if (m0 >= cnt) return;

    int n0 = blockIdx.x * BN;
    const __half* B = B1b + (size_t)e * strideB;
    __half* Ch = C1h;
    const int N = N1;

    extern __shared__ __half smh[];
    __shared__ int rowmap[BM];

    const int tid = threadIdx.x;
    if (tid < BM) {
        int r = m0 + tid;
        int gr = -1;
        if (r < cnt) gr = gather ? gather[start + r] : (start + r);
        rowmap[tid] = gr;
    }
    __syncthreads();

    const int warp = tid >> 5, lane = tid & 31;
    const int g = lane >> 2, tig = lane & 3;
    const int warp_m = (warp & 1) * 64, warp_n = (warp >> 1) * 32;

    float acc[4][4][4];
#pragma unroll
    for (int a = 0; a < 4; a++)
#pragma unroll
        for (int b = 0; b < 4; b++)
#pragma unroll
            for (int c = 0; c < 4; c++) acc[a][b][c] = 0.f;

    const int nk = K / BK;
    uint32_t smA[NSTG], smB[NSTG];
#pragma unroll
    for (int s = 0; s < NSTG; s++) {
        smA[s] = (uint32_t)__cvta_generic_to_shared(smh + s * BM * SKS);
        smB[s] = (uint32_t)__cvta_generic_to_shared(smh + NSTG * BM * SKS + s * BN * SKS);
    }

    const int ldrow = tid >> 3, ldc8 = (tid & 7) << 3;
    const int grow[4] = { rowmap[ldrow], rowmap[ldrow + 32], rowmap[ldrow + 64], rowmap[ldrow + 96] };
    const uint32_t aoff = ((warp_m + (lane & 15)) * SKS + ((lane >> 4) << 3)) * 2;
    const uint32_t boff = ((warp_n + ((lane >> 4) & 1) * 8 + (lane & 7)) * SKS
                           + (((lane >> 3) & 1) << 3)) * 2;

#pragma unroll
    for (int s = 0; s < 2; s++) {
        int k0 = s * BK;
#pragma unroll
        for (int i = 0; i < 4; i++) {
            int row = ldrow + i * 32;
            const __half* src = (grow[i] >= 0) ? (A + (size_t)grow[i] * K + k0 + ldc8) : A;
            cp16(smA[s] + (row * SKS + ldc8) * 2, src, (grow[i] >= 0) ? 16 : 0);
        }
#pragma unroll
        for (int i = 0; i < 4; i++) {
            int row = ldrow + i * 32;
            cp16(smB[s] + (row * SKS + ldc8) * 2, B + (size_t)(n0 + row) * K + k0 + ldc8, 16);
        }
        cp_commit();
    }

    int cur = 0, pf = 2;
    for (int kt = 0; kt < nk; kt++) {
        cp_wait1();
        __syncthreads();
        if (kt + 2 < nk) {
            int k0 = (kt + 2) * BK;
#pragma unroll
            for (int i = 0; i < 4; i++) {
                int row = ldrow + i * 32;
                const __half* src = (grow[i] >= 0) ? (A + (size_t)grow[i] * K + k0 + ldc8) : A;
                cp16(smA[pf] + (row * SKS + ldc8) * 2, src, (grow[i] >= 0) ? 16 : 0);
            }
#pragma unroll
            for (int i = 0; i < 4; i++) {
                int row = ldrow + i * 32;
                cp16(smB[pf] + (row * SKS + ldc8) * 2, B + (size_t)(n0 + row) * K + k0 + ldc8, 16);
            }
        }
        cp_commit();

        const uint32_t sA = smA[cur], sB = smB[cur];
#pragma unroll
        for (int ks = 0; ks < 4; ks++) {
            const uint32_t kk2 = ks * 32;
            uint32_t af[4][4], bf[4][2];
#pragma unroll
            for (int mt = 0; mt < 4; mt++)
                ldm_x4(af[mt], sA + aoff + mt * 16 * SKS * 2 + kk2);
#pragma unroll
            for (int ntp = 0; ntp < 2; ntp++) {
                uint32_t tmp[4];
                ldm_x4(tmp, sB + boff + ntp * 16 * SKS * 2 + kk2);
                bf[2 * ntp][0] = tmp[0]; bf[2 * ntp][1] = tmp[1];
                bf[2 * ntp + 1][0] = tmp[2]; bf[2 * ntp + 1][1] = tmp[3];
            }
#pragma unroll
            for (int mt = 0; mt < 4; mt++)
#pragma unroll
                for (int nt = 0; nt < 4; nt++)
                    mma_h(acc[mt][nt], af[mt], bf[nt]);
        }
        cur = (cur + 1 == NSTG) ? 0 : cur + 1;
        pf = (pf + 1 == NSTG) ? 0 : pf + 1;
    }

#pragma unroll
    for (int mt = 0; mt < 4; mt++) {
        int r = warp_m + mt * 16 + g;
#pragma unroll
        for (int nt = 0; nt < 4; nt++) {
            int gc = n0 + warp_n + nt * 8 + tig * 2;
            if (m0 + r < cnt)
                *(__half2*)(Ch + (size_t)(start + m0 + r) * N + gc) =
                    __floats2half2_rn(acc[mt][nt][0], acc[mt][nt][1]);
            if (m0 + r + 8 < cnt)
                *(__half2*)(Ch + (size_t)(start + m0 + r + 8) * N + gc) =
                    __floats2half2_rn(acc[mt][nt][2], acc[mt][nt][3]);
        }
    }
}

// ---------------- fused gate+up+SiLU MoE GEMM ----------------
// Tile 128 x 64; computes G = A@Bg^T and U = A@Bu^T simultaneously,
// writes silu(G)*U. Serves both routed experts (gather=tok) and shared expert
// (gather=nullptr, off={0,SEQ}, e=0).
__global__ __launch_bounds__(256, 2) void gemm_h_moe_fused(
    const __half* __restrict__ A, const int* __restrict__ gather,
    const __half* __restrict__ Bgb, const __half* __restrict__ Bub,
    __half* __restrict__ Cact, int N, size_t strideB, int K,
    const int* __restrict__ off)
{
    const int e = blockIdx.z;
    const int start = off[e];
    const int cnt = off[e + 1] - start;
    const int m0 = blockIdx.y * BM;
    if (m0 >= cnt) return;

    const int n0 = blockIdx.x * BNF;
    const __half* Bg = Bgb + (size_t)e * strideB;
    const __half* Bu = Bub + (size_t)e * strideB;

    extern __shared__ __half smh[];
    __shared__ int rowmap[BM];

    const int tid = threadIdx.x;
    if (tid < BM) {
        int r = m0 + tid;
        int gr = -1;
        if (r < cnt) gr = gather ? gather[start + r] : (start + r);
        rowmap[tid] = gr;
    }
    __syncthreads();

    const int warp = tid >> 5, lane = tid & 31;
    const int g = lane >> 2, tig = lane & 3;
    const int warp_m = (warp & 1) * 64, warp_n = (warp >> 1) * 16;

    float accG[4][2][4], accU[4][2][4];
#pragma unroll
    for (int a = 0; a < 4; a++)
#pragma unroll
        for (int b = 0; b < 2; b++)
#pragma unroll
            for (int c = 0; c < 4; c++) { accG[a][b][c] = 0.f; accU[a][b][c] = 0.f; }

    const int nk = K / BK;
    uint32_t smA[NSTG], smG[NSTG], smU[NSTG];
#pragma unroll
    for (int s = 0; s < NSTG; s++) {
        smA[s] = (uint32_t)__cvta_generic_to_shared(smh + s * BM * SKS);
        smG[s] = (uint32_t)__cvta_generic_to_shared(smh + NSTG * BM * SKS + s * BNF * SKS);
        smU[s] = (uint32_t)__cvta_generic_to_shared(smh + NSTG * (BM + BNF) * SKS + s * BNF * SKS);
    }

    const int ldrow = tid >> 3, ldc8 = (tid & 7) << 3;   // A rows 0..31 (+32i); B rows 0..31 for i<2
    const int grow[4] = { rowmap[ldrow], rowmap[ldrow + 32], rowmap[ldrow + 64], rowmap[ldrow + 96] };
    const uint32_t aoff = ((warp_m + (lane & 15)) * SKS + ((lane >> 4) << 3)) * 2;
    const uint32_t boff = ((warp_n + ((lane >> 4) & 1) * 8 + (lane & 7)) * SKS
                           + (((lane >> 3) & 1) << 3)) * 2;

#pragma unroll
    for (int s = 0; s < 2; s++) {
        int k0 = s * BK;
#pragma unroll
        for (int i = 0; i < 4; i++) {
            int row = ldrow + i * 32;
            const __half* src = (grow[i] >= 0) ? (A + (size_t)grow[i] * K + k0 + ldc8) : A;
            cp16(smA[s] + (row * SKS + ldc8) * 2, src, (grow[i] >= 0) ? 16 : 0);
        }
#pragma unroll
        for (int i = 0; i < 2; i++) {
            int row = ldrow + i * 32;
            cp16(smG[s] + (row * SKS + ldc8) * 2, Bg + (size_t)(n0 + row) * K + k0 + ldc8, 16);
            cp16(smU[s] + (row * SKS + ldc8) * 2, Bu + (size_t)(n0 + row) * K + k0 + ldc8, 16);
        }
        cp_commit();
    }

    int cur = 0, pf = 2;
    for (int kt = 0; kt < nk; kt++) {
        cp_wait1();
        __syncthreads();
        if (kt + 2 < nk) {
            int k0 = (kt + 2) * BK;
#pragma unroll
            for (int i = 0; i < 4; i++) {
                int row = ldrow + i * 32;
                const __half* src = (grow[i] >= 0) ? (A + (size_t)grow[i] * K + k0 + ldc8) : A;
                cp16(smA[pf] + (row * SKS + ldc8) * 2, src, (grow[i] >= 0) ? 16 : 0);
            }
#pragma unroll
            for (int i = 0; i < 2; i++) {
                int row = ldrow + i * 32;
                cp16(smG[pf] + (row * SKS + ldc8) * 2, Bg + (size_t)(n0 + row) * K + k0 + ldc8, 16);
                cp16(smU[pf] + (row * SKS + ldc8) * 2, Bu + (size_t)(n0 + row) * K + k0 + ldc8, 16);
            }
        }
        cp_commit();

        const uint32_t sA = smA[cur], sG = smG[cur], sU = smU[cur];
#pragma unroll
        for (int ks = 0; ks < 4; ks++) {
            const uint32_t kk2 = ks * 32;
            uint32_t af[4][4], bg[4], bu[4];
#pragma unroll
            for (int mt = 0; mt < 4; mt++)
                ldm_x4(af[mt], sA + aoff + mt * 16 * SKS * 2 + kk2);
            ldm_x4(bg, sG + boff + kk2);
            ldm_x4(bu, sU + boff + kk2);
#pragma unroll
            for (int mt = 0; mt < 4; mt++) {
                mma_h(accG[mt][0], af[mt], bg);
                mma_h(accG[mt][1], af[mt], bg + 2);
                mma_h(accU[mt][0], af[mt], bu);
                mma_h(accU[mt][1], af[mt], bu + 2);
            }
        }
        cur = (cur + 1 == NSTG) ? 0 : cur + 1;
        pf = (pf + 1 == NSTG) ? 0 : pf + 1;
    }

#pragma unroll
    for (int mt = 0; mt < 4; mt++) {
        int r = warp_m + mt * 16 + g;
#pragma unroll
        for (int nt = 0; nt < 2; nt++) {
            int gc = n0 + warp_n + nt * 8 + tig * 2;
            float v0 = silu_mul(accG[mt][nt][0], accU[mt][nt][0]);
            float v1 = silu_mul(accG[mt][nt][1], accU[mt][nt][1]);
            float v2 = silu_mul(accG[mt][nt][2], accU[mt][nt][2]);
            float v3 = silu_mul(accG[mt][nt][3], accU[mt][nt][3]);
            if (m0 + r < cnt)
                *(__half2*)(Cact + (size_t)(start + m0 + r) * N + gc) = __floats2half2_rn(v0, v1);
            if (m0 + r + 8 < cnt)
                *(__half2*)(Cact + (size_t)(start + m0 + r + 8) * N + gc) = __floats2half2_rn(v2, v3);
        }
    }
}

// ---------------- fp16 flash attention ----------------
__global__ __launch_bounds__(256) void attn_h_kernel() {
    extern __shared__ __half smh[];
    __half* Qs  = smh;
    __half* Ksb = Qs + AQ * QST;
    __half* Vsb = Ksb + 2 * AK * KST;
    __half* Ps  = Vsb + 2 * AK * VST;

    const int h = blockIdx.y;
    const int qb = gridDim.x - 1 - blockIdx.x;
    const int q0 = qb * AQ;
    const int tid = threadIdx.x;
    const int warp = tid >> 5, lane = tid & 31;
    const int g = lane >> 2, tig = lane & 3;
    const int row0 = warp * 16 + g;
    const int qi0 = q0 + row0, qi1 = qi0 + 8;

    uint32_t smK[2], smV[2];
    smK[0] = (uint32_t)__cvta_generic_to_shared(Ksb);
    smK[1] = (uint32_t)__cvta_generic_to_shared(Ksb + AK * KST);
    smV[0] = (uint32_t)__cvta_generic_to_shared(Vsb);
    smV[1] = (uint32_t)__cvta_generic_to_shared(Vsb + AK * VST);
    const uint32_t smQ = (uint32_t)__cvta_generic_to_shared(Qs);
    const uint32_t smP = (uint32_t)__cvta_generic_to_shared(Ps);

    const uint32_t qoff = smQ + ((warp * 16 + (lane & 15)) * QST + ((lane >> 4) << 3)) * 2;
    const uint32_t koff = ((((lane >> 4) & 1) * 8 + (lane & 7)) * KST
                            + (((lane >> 3) & 1) << 3)) * 2;
    const uint32_t poff = smP + ((warp * 16 + (lane & 15)) * PST + ((lane >> 4) << 3)) * 2;
    const uint32_t voff = ((lane & 15) * VST + ((lane >> 4) & 1) * 8) * 2;

#pragma unroll
    for (int i = 0; i < 12; i++) {
        int idx = tid + i * 256;
        int r = idx / 24, c = (idx % 24) * 8;
        *(float4*)(Qs + r * QST + c) =
            *(const float4*)(a_q + ((size_t)(q0 + r) * NHEAD + h) * DQK + c);
    }

    float acc[16][4];
#pragma unroll
    for (int n = 0; n < 16; n++)
#pragma unroll
        for (int c = 0; c < 4; c++) acc[n][c] = 0.f;
    float m0 = -1e30f, m1 = -1e30f, l0 = 0.f, l1 = 0.f;
    const float scale = 0.07216878364870323f;

    const int ntiles = qb * 2 + 2;

    {
#pragma unroll
        for (int i = 0; i < 6; i++) {
            int idx = tid + i * 256;
            int r = idx / 24, c = (idx % 24) * 8;
            cp16(smK[0] + (r * KST + c) * 2,
                 a_kv + ((size_t)r * NHEAD + h) * (DQK + DV) + c, 16);
        }
#pragma unroll
        for (int i = 0; i < 4; i++) {
            int idx = tid + i * 256;
            int r = idx >> 4, c = (idx & 15) * 8;
            cp16(smV[0] + (r * VST + c) * 2,
                 a_kv + ((size_t)r * NHEAD + h) * (DQK + DV) + DQK + c, 16);
        }
        cp_commit();
    }

    for (int tile = 0; tile < ntiles; tile++) {
        const int cur = tile & 1, nb = cur ^ 1;
        __syncthreads();
        if (tile + 1 < ntiles) {
            int t1 = (tile + 1) * AK;
#pragma unroll
            for (int i = 0; i < 6; i++) {
                int idx = tid + i * 256;
                int r = idx / 24, c = (idx % 24) * 8;
                cp16(smK[nb] + (r * KST + c) * 2,
                     a_kv + ((size_t)(t1 + r) * NHEAD + h) * (DQK + DV) + c, 16);
            }
#pragma unroll
            for (int i = 0; i < 4; i++) {
                int idx = tid + i * 256;
                int r = idx >> 4, c = (idx & 15) * 8;
                cp16(smV[nb] + (r * VST + c) * 2,
                     a_kv + ((size_t)(t1 + r) * NHEAD + h) * (DQK + DV) + DQK + c, 16);
            }
            cp_commit();
            cp_wait1();
        } else {
            cp_wait0();
        }
        __syncthreads();

        const int t0 = tile * AK;
        float s[8][4];
#pragma unroll
        for (int n = 0; n < 8; n++)
#pragma unroll
            for (int c = 0; c < 4; c++) s[n][c] = 0.f;
#pragma unroll
        for (int ks = 0; ks < 12; ks++) {
            const uint32_t kk2 = ks * 32;
            uint32_t af[4];
            ldm_x4(af, qoff + kk2);
#pragma unroll
            for (int ntp = 0; ntp < 4; ntp++) {
                uint32_t tmp[4];
                ldm_x4(tmp, smK[cur] + koff + ntp * 16 * KST * 2 + kk2);
                mma_h(s[2 * ntp],     af, tmp);
                mma_h(s[2 * ntp + 1], af, tmp + 2);
            }
        }

        const bool domask = (t0 + AK - 1 > q0);
#pragma unroll
        for (int nt = 0; nt < 8; nt++) {
#pragma unroll
            for (int c = 0; c < 4; c++) s[nt][c] *= scale;
            if (domask) {
                int kj = t0 + nt * 8 + tig * 2;
                if (kj > qi0)     s[nt][0] = -1e30f;
                if (kj + 1 > qi0) s[nt][1] = -1e30f;
                if (kj > qi1)     s[nt][2] = -1e30f;
                if (kj + 1 > qi1) s[nt][3] = -1e30f;
            }
        }

        float mx0 = -1e30f, mx1 = -1e30f;
#pragma unroll
        for (int nt = 0; nt < 8; nt++) {
            mx0 = fmaxf(mx0, fmaxf(s[nt][0], s[nt][1]));
            mx1 = fmaxf(mx1, fmaxf(s[nt][2], s[nt][3]));
        }
        mx0 = fmaxf(mx0, __shfl_xor_sync(0xffffffffu, mx0, 1));
        mx0 = fmaxf(mx0, __shfl_xor_sync(0xffffffffu, mx0, 2));
        mx1 = fmaxf(mx1, __shfl_xor_sync(0xffffffffu, mx1, 1));
        mx1 = fmaxf(mx1, __shfl_xor_sync(0xffffffffu, mx1, 2));

        float mn0 = fmaxf(m0, mx0), mn1 = fmaxf(m1, mx1);
        float cf0 = __expf(m0 - mn0), cf1 = __expf(m1 - mn1);
        m0 = mn0; m1 = mn1;

        float sum0 = 0.f, sum1 = 0.f;
#pragma unroll
        for (int nt = 0; nt < 8; nt++) {
            float p0 = __expf(s[nt][0] - m0);
            float p1 = __expf(s[nt][1] - m0);
            float p2 = __expf(s[nt][2] - m1);
            float p3 = __expf(s[nt][3] - m1);
            sum0 += p0 + p1; sum1 += p2 + p3;
            *(__half2*)(Ps + row0 * PST + nt * 8 + tig * 2) = __floats2half2_rn(p0, p1);
            *(__half2*)(Ps + (row0 + 8) * PST + nt * 8 + tig * 2) = __floats2half2_rn(p2, p3);
        }
        sum0 += __shfl_xor_sync(0xffffffffu, sum0, 1);
        sum0 += __shfl_xor_sync(0xffffffffu, sum0, 2);
        sum1 += __shfl_xor_sync(0xffffffffu, sum1, 1);
        sum1 += __shfl_xor_sync(0xffffffffu, sum1, 2);
        l0 = l0 * cf0 + sum0;
        l1 = l1 * cf1 + sum1;
#pragma unroll
        for (int nt = 0; nt < 16; nt++) {
            acc[nt][0] *= cf0; acc[nt][1] *= cf0;
            acc[nt][2] *= cf1; acc[nt][3] *= cf1;
        }
        __syncwarp();

#pragma unroll
        for (int ks = 0; ks < 4; ks++) {
            uint32_t af[4];
            ldm_x4(af, poff + ks * 32);
            const uint32_t vbase = smV[cur] + voff + (uint32_t)(ks * 16) * VST * 2;
#pragma unroll
            for (int ntp = 0; ntp < 8; ntp++) {
                uint32_t tmp[4];
                ldm_x4_t(tmp, vbase + ntp * 16 * 2);
                mma_h(acc[2 * ntp],     af, tmp);
                mma_h(acc[2 * ntp + 1], af, tmp + 2);
            }
        }
    }

    float inv0 = 1.0f / l0, inv1 = 1.0f / l1;
#pragma unroll
    for (int nt = 0; nt < 16; nt++) {
        int col = h * DV + nt * 8 + tig * 2;
        *(__half2*)(a_ctx + (size_t)qi0 * (NHEAD * DV) + col) =
            __floats2half2_rn(acc[nt][0] * inv0, acc[nt][1] * inv0);
        *(__half2*)(a_ctx + (size_t)qi1 * (NHEAD * DV) + col) =
            __floats2half2_rn(acc[nt][2] * inv1, acc[nt][3] * inv1);
    }
}

// ---------------- RMSNorm: warp per row, no barriers ----------------
__global__ void rmsnorm_h(const float* in, const float* w, __half* out, float* outf, int D) {
    const int t = blockIdx.x * 8 + (threadIdx.x >> 5);
    const int lane = threadIdx.x & 31;
    const float4* row = (const float4*)(in + (size_t)t * D);
    const int n4 = D >> 2;
    float ss = 0.f;
    for (int i = lane; i < n4; i += 32) {
        float4 v = row[i];
        ss += v.x * v.x + v.y * v.y + v.z * v.z + v.w * v.w;
    }
#pragma unroll
    for (int o = 16; o > 0; o >>= 1) ss += __shfl_xor_sync(0xffffffffu, ss, o);
    const float scale = 1.0f / sqrtf(ss / (float)D + 1e-6f);
    for (int i = lane; i < n4; i += 32) {
        float4 v = row[i];
        const float4 wv = *(const float4*)(w + 4 * i);
        float r0 = v.x * scale * wv.x, r1 = v.y * scale * wv.y;
        float r2 = v.z * scale * wv.z, r3 = v.w * scale * wv.w;
        __half2 p[2];
        p[0] = __floats2half2_rn(r0, r1);
        p[1] = __floats2half2_rn(r2, r3);
        *(float2*)(out + (size_t)t * D + 4 * i) = *(float2*)p;
        if (outf) *(float4*)(outf + (size_t)t * D + 4 * i) = make_float4(r0, r1, r2, r3);
    }
}

// ---------------- RoPE ----------------
__global__ void rope_h_kernel() {
    int idx = blockIdx.x * blockDim.x + threadIdx.x;
    int total = SEQ * NHEAD * (ROPED / 2);
    if (idx >= total) return;
    int i = idx & 31;
    int h = (idx >> 5) & (NHEAD - 1);
    int t = idx >> 9;
    float inv_freq = powf(10000.0f, -(float)(2 * i) / (float)ROPED);
    float f = (float)t * inv_freq;
    float c = cosf(f), s = sinf(f);
    __half* qp = a_q + ((size_t)t * NHEAD + h) * DQK + NOPE;
    float x1 = __half2float(qp[i]), x2 = __half2float(qp[i + 32]);
    qp[i] = __float2half(x1 * c - x2 * s);
    qp[i + 32] = __float2half(x2 * c + x1 * s);
    __half* kp = a_kv + ((size_t)t * NHEAD + h) * (DQK + DV) + NOPE;
    x1 = __half2float(kp[i]); x2 = __half2float(kp[i + 32]);
    kp[i] = __float2half(x1 * c - x2 * s);
    kp[i + 32] = __float2half(x2 * c + x1 * s);
}

// ---------------- Router (fp32 h2) — also zeroes expert counters ----------------
__global__ void router_kernel(const float* __restrict__ rw, const float* __restrict__ rb) {
    int t = blockIdx.x;
    if (t == 0 && threadIdx.x < NEXP) { g_cnt[threadIdx.x] = 0; g_fill[threadIdx.x] = 0; }
    float part[NEXP];
#pragma unroll
    for (int e = 0; e < NEXP; e++) part[e] = 0.f;
    for (int hh = threadIdx.x; hh < HDIM; hh += 128) {
        float xv = g_h2f[(size_t)t * HDIM + hh];
#pragma unroll
        for (int e = 0; e < NEXP; e++) part[e] += xv * rw[(size_t)e * HDIM + hh];
    }
    __shared__ float sred[4][NEXP];
#pragma unroll
    for (int e = 0; e < NEXP; e++)
        for (int o = 16; o > 0; o >>= 1) part[e] += __shfl_down_sync(0xffffffffu, part[e], o);
    int lane = threadIdx.x & 31, warp = threadIdx.x >> 5;
    if (lane == 0)
#pragma unroll
        for (int e = 0; e < NEXP; e++) sred[warp][e] = part[e];
    __syncthreads();
    if (threadIdx.x < NEXP) {
        int e = threadIdx.x;
        g_logits[t * NEXP + e] = sred[0][e] + sred[1][e] + sred[2][e] + sred[3][e] + rb[e];
    }
}

__global__ void topk_kernel() {
    int t = blockIdx.x * blockDim.x + threadIdx.x;
    if (t >= SEQ) return;
    float p[NEXP];
#pragma unroll
    for (int e = 0; e < NEXP; e++) p[e] = 1.0f / (1.0f + expf(-g_logits[t * NEXP + e]));
    float vals[TOPK]; int ids[TOPK];
    float sum = 0.f;
#pragma unroll
    for (int k = 0; k < TOPK; k++) {
        float best = -1e30f; int bi = 0;
#pragma unroll
        for (int e = 0; e < NEXP; e++)
            if (p[e] > best) { best = p[e]; bi = e; }
        vals[k] = best; ids[k] = bi; p[bi] = -1e30f; sum += best;
    }
    float w = 2.5f / (sum + 1e-9f);
#pragma unroll
    for (int k = 0; k < TOPK; k++) {
        g_wtop[t * TOPK + k] = vals[k] * w;
        g_topi[t * TOPK + k] = ids[k];
        atomicAdd(&g_cnt[ids[k]], 1);
    }
}

__global__ void offsets_kernel() {
    if (threadIdx.x == 0) {
        g_off[0] = 0;
        for (int e = 0; e < NEXP; e++) g_off[e + 1] = g_off[e] + g_cnt[e];
    }
}

__global__ void scatter_kernel() {
    int t = blockIdx.x * blockDim.x + threadIdx.x;
    if (t >= SEQ) return;
#pragma unroll
    for (int k = 0; k < TOPK; k++) {
        int e = g_topi[t * TOPK + k];
        int pos = atomicAdd(&g_fill[e], 1);
        int slot = g_off[e] + pos;
        g_slot[t * TOPK + k] = slot;
        g_tok[slot] = t;
    }
}

// ---------------- Final combine (float4) ----------------
__global__ void combine_kernel(float* out) {
    int t = blockIdx.x;
    float w[TOPK]; int s[TOPK];
#pragma unroll
    for (int k = 0; k < TOPK; k++) { w[k] = g_wtop[t * TOPK + k]; s[k] = g_slot[t * TOPK + k]; }
    for (int i = threadIdx.x; i < HDIM / 4; i += 256) {
        float4 v = *(const float4*)(g_xmid + (size_t)t * HDIM + 4 * i);
        float4 sh = *(const float4*)(g_shr + (size_t)t * HDIM + 4 * i);
        v.x += sh.x; v.y += sh.y; v.z += sh.z; v.w += sh.w;
#pragma unroll
        for (int k = 0; k < TOPK; k++) {
            float2 d01 = __half22float2(*(const __half2*)(a_down + (size_t)s[k] * HDIM + 4 * i));
            float2 d23 = __half22float2(*(const __half2*)(a_down + (size_t)s[k] * HDIM + 4 * i + 2));
            v.x += w[k] * d01.x; v.y += w[k] * d01.y;
            v.z += w[k] * d23.x; v.w += w[k] * d23.y;
        }
        *(float4*)(out + (size_t)t * HDIM + 4 * i) = v;
    }
}

// ---------------- host ----------------
static float* symf(const void* sym) { void* p = nullptr; cudaGetSymbolAddress(&p, sym); return (float*)p; }
static __half* symh(const void* sym) { void* p = nullptr; cudaGetSymbolAddress(&p, sym); return (__half*)p; }
static int*   symi(const void* sym) { void* p = nullptr; cudaGetSymbolAddress(&p, sym); return (int*)p; }

extern "C" void kernel_launch(void* const* d_in, const int* in_sizes, int n_in,
                              void* d_out, int out_size)
{
    const float* x      = (const float*)d_in[0];
    const float* ln1_w  = (const float*)d_in[2];
    const float* ln2_w  = (const float*)d_in[3];
    const float* q_a_w  = (const float*)d_in[4];
    const float* q_a_ln = (const float*)d_in[5];
    const float* q_b_w  = (const float*)d_in[6];
    const float* kv_a_w = (const float*)d_in[7];
    const float* kv_a_ln= (const float*)d_in[8];
    const float* kv_b_w = (const float*)d_in[9];
    const float* o_w    = (const float*)d_in[10];
    const float* rout_w = (const float*)d_in[11];
    const float* rout_b = (const float*)d_in[12];
    const float* gate_w = (const float*)d_in[13];
    const float* up_w   = (const float*)d_in[14];
    const float* down_w = (const float*)d_in[15];
    const float* sg_w   = (const float*)d_in[16];
    const float* su_w   = (const float*)d_in[17];
    const float* sd_w   = (const float*)d_in[18];
    float* out = (float*)d_out;

    __half* wqa  = symh(w_qa);   __half* wkva = symh(w_kva);
    __half* wqb  = symh(w_qb);   __half* wkvb = symh(w_kvb);
    __half* wo   = symh(w_o);
    __half* wg   = symh(w_gate); __half* wu   = symh(w_up);  __half* wd = symh(w_down);
    __half* wsg  = symh(w_sg);   __half* wsu  = symh(w_su);  __half* wsd = symh(w_sd);

    __half* h1h  = symh(a_h1);
    __half* qah  = symh(a_qa);   __half* kvah = symh(a_kva);
    __half* qh   = symh(a_q);    __half* kvh  = symh(a_kv);
    __half* ctxh = symh(a_ctx);  __half* h2h  = symh(a_h2);
    __half* gth  = symh(a_gate);
    __half* dnh  = symh(a_down);
    __half* sgh  = symh(a_sg);

    float* qaf  = symf(g_qa);   float* kvaf = symf(g_kva);
    float* xmid = symf(g_xmid); float* h2f  = symf(g_h2f);
    float* shr  = symf(g_shr);
    int* tok = symi(g_tok);     int* off = symi(g_off);
    int* offsh = symi(g_off_shared);

    cudaFuncSetAttribute(gemm_h, cudaFuncAttributeMaxDynamicSharedMemorySize, GSMEM);
    cudaFuncSetAttribute(gemm_h_moe, cudaFuncAttributeMaxDynamicSharedMemorySize, GSMEM);
    cudaFuncSetAttribute(gemm_h_moe_fused, cudaFuncAttributeMaxDynamicSharedMemorySize, GSMEM);
    cudaFuncSetAttribute(attn_h_kernel, cudaFuncAttributeMaxDynamicSharedMemorySize, ATTN_SMEM);

    // ---- batched weight conversion (one launch) ----
    {
        ConvBatch cb;
        const float* ins[NSEG] = { q_a_w, kv_a_w, q_b_w, kv_b_w, o_w,
                                   gate_w, up_w, down_w, sg_w, su_w, sd_w };
        __half* outs[NSEG] = { wqa, wkva, wqb, wkvb, wo, wg, wu, wd, wsg, wsu, wsd };
        size_t ns[NSEG] = {
            (size_t)QRNK * HDIM, (size_t)KVRNK * HDIM,
            (size_t)NHEAD * DQK * QRNK, (size_t)NHEAD * (DQK + DV) * KVRNK,
            (size_t)HDIM * NHEAD * DV,
            (size_t)NEXP * MINT * HDIM, (size_t)NEXP * MINT * HDIM,
            (size_t)NEXP * HDIM * MINT,
            (size_t)MINT * HDIM, (size_t)MINT * HDIM, (size_t)HDIM * MINT };
        int acc = 0;
        for (int s = 0; s < NSEG; s++) {
            cb.in[s] = (const float4*)ins[s];
            cb.out[s] = outs[s];
            cb.start[s] = acc;
            acc += (int)(ns[s] / 4);
        }
        cb.start[NSEG] = acc;
        conv_batch_kernel<<<(acc + 255) / 256, 256>>>(cb);
    }

    // ---- attention branch ----
    rmsnorm_h<<<SEQ / 8, 256>>>(x, ln1_w, h1h, nullptr, HDIM);
    gemm_h<<<dim3((QRNK + KVRNK) / BN, SEQ / BM), 256, GSMEM>>>(
        h1h, wqa, qaf, nullptr, nullptr, QRNK, HDIM,
        h1h, wkva, kvaf, nullptr, KVRNK, HDIM, SEQ);
    rmsnorm_h<<<SEQ / 8, 256>>>(qaf, q_a_ln, qah, nullptr, QRNK);
    rmsnorm_h<<<SEQ / 8, 256>>>(kvaf, kv_a_ln, kvah, nullptr, KVRNK);
    gemm_h<<<dim3((NHEAD * DQK + NHEAD * (DQK + DV)) / BN, SEQ / BM), 256, GSMEM>>>(
        qah, wqb, nullptr, qh, nullptr, NHEAD * DQK, QRNK,
        kvah, wkvb, nullptr, kvh, NHEAD * (DQK + DV), KVRNK, SEQ);
    rope_h_kernel<<<(SEQ * NHEAD * (ROPED / 2) + 255) / 256, 256>>>();
    attn_h_kernel<<<dim3(SEQ / AQ, NHEAD), 256, ATTN_SMEM>>>();
    gemm_h<<<dim3(HDIM / BN, SEQ / BM), 256, GSMEM>>>(
        ctxh, wo, xmid, nullptr, x, HDIM, NHEAD * DV,
        nullptr, nullptr, nullptr, nullptr, 0, BK, SEQ);

    // ---- MoE branch ----
    rmsnorm_h<<<SEQ / 8, 256>>>(xmid, ln2_w, h2h, h2f, HDIM);
    router_kernel<<<SEQ, 128>>>(rout_w, rout_b);
    topk_kernel<<<SEQ / 256, 256>>>();
    offsets_kernel<<<1, 1>>>();
    scatter_kernel<<<SEQ / 256, 256>>>();

    // fused gate+up+silu (routed experts)
    gemm_h_moe_fused<<<dim3(MINT / BNF, SEQ / BM, NEXP), 256, GSMEM>>>(
        h2h, tok, wg, wu, gth, MINT, (size_t)MINT * HDIM, HDIM, off);
    // down projection
    gemm_h_moe<<<dim3(HDIM / BN, SEQ / BM, NEXP), 256, GSMEM>>>(
        gth, nullptr, wd, dnh, HDIM, (size_t)HDIM * MINT, MINT, off);

    // shared expert: fused sg+su+silu, then sd
    gemm_h_moe_fused<<<dim3(MINT / BNF, SEQ / BM, 1), 256, GSMEM>>>(
        h2h, nullptr, wsg, wsu, sgh, MINT, 0, HDIM, offsh);
    gemm_h<<<dim3(HDIM / BN, SEQ / BM), 256, GSMEM>>>(
        sgh, wsd, shr, nullptr, nullptr, HDIM, MINT,
        nullptr, nullptr, nullptr, nullptr, 0, BK, SEQ);

    combine_kernel<<<SEQ, 256>>>(out);
}